// round 12
// baseline (speedup 1.0000x reference)
#include <cuda_runtime.h>
#include <cuda_bf16.h>
#include <cstdint>

// ============================================================================
// Attention_84129819394524 — R4 GEMMs (proven 483us) + softmax FUSED into the
// S kernel: one block per (128-row strip, head); pass1 = 8 logit tiles via the
// unchanged R4 mainloop (tracking row maxes in regs), pass2 = L2-hot re-read
// of the strip -> row sums -> normalize -> write fp32 attn + bf16 ph/pl.
// Kills the standalone softmax kernel's DRAM round trip.
// ============================================================================

#define NUM_HEADS 12
#define HEAD_DIM  64
#define DIMC      768
#define BATCH     4
#define SEQ       1024
#define SCALE_F   0.125f

#define M_TOK   (BATCH * SEQ)          // 4096
#define QKV_N   (3 * DIMC)             // 2304
#define BH      (BATCH * NUM_HEADS)    // 48

#define OUT_ELEMS  ((size_t)M_TOK * DIMC)
#define ATTN_ELEMS ((size_t)BH * SEQ * SEQ)

// ---------------- device scratch (allocation-free) ----------------
__device__ __align__(16) __nv_bfloat16 g_xh [M_TOK * DIMC];
__device__ __align__(16) __nv_bfloat16 g_xl [M_TOK * DIMC];
__device__ __align__(16) __nv_bfloat16 g_wqh[QKV_N * DIMC];
__device__ __align__(16) __nv_bfloat16 g_wql[QKV_N * DIMC];
__device__ __align__(16) __nv_bfloat16 g_wph[DIMC * DIMC];
__device__ __align__(16) __nv_bfloat16 g_wpl[DIMC * DIMC];
__device__ __align__(16) __nv_bfloat16 g_qh [BH * SEQ * HEAD_DIM];
__device__ __align__(16) __nv_bfloat16 g_ql [BH * SEQ * HEAD_DIM];
__device__ __align__(16) __nv_bfloat16 g_kh [BH * SEQ * HEAD_DIM];
__device__ __align__(16) __nv_bfloat16 g_kl [BH * SEQ * HEAD_DIM];
__device__ __align__(16) __nv_bfloat16 g_vh [BH * SEQ * HEAD_DIM];
__device__ __align__(16) __nv_bfloat16 g_vl [BH * SEQ * HEAD_DIM];
__device__ __align__(16) __nv_bfloat16 g_vth[BH * HEAD_DIM * SEQ];
__device__ __align__(16) __nv_bfloat16 g_vtl[BH * HEAD_DIM * SEQ];
__device__ __align__(16) __nv_bfloat16 g_ph [BH * SEQ * SEQ];
__device__ __align__(16) __nv_bfloat16 g_pl [BH * SEQ * SEQ];
__device__ __align__(16) __nv_bfloat16 g_oh [M_TOK * DIMC];
__device__ __align__(16) __nv_bfloat16 g_ol [M_TOK * DIMC];
__device__ __align__(256) float g_attn[ATTN_ELEMS];
__device__ __align__(256) float g_outs[OUT_ELEMS];

// ---------------- helpers ----------------
__device__ __forceinline__ uint32_t smem_u32(const void* p) {
    return (uint32_t)__cvta_generic_to_shared(p);
}
__device__ __forceinline__ void cpasync16(uint32_t dst, const void* src) {
    asm volatile("cp.async.cg.shared.global [%0], [%1], 16;" :: "r"(dst), "l"(src));
}
__device__ __forceinline__ void ldsm_x4(uint32_t* r, uint32_t addr) {
    asm volatile("ldmatrix.sync.aligned.m8n8.x4.shared.b16 {%0,%1,%2,%3}, [%4];"
                 : "=r"(r[0]), "=r"(r[1]), "=r"(r[2]), "=r"(r[3]) : "r"(addr));
}
__device__ __forceinline__ void mma16816(float* c, const uint32_t* a, const uint32_t* b) {
    asm volatile("mma.sync.aligned.m16n8k16.row.col.f32.bf16.bf16.f32 "
                 "{%0,%1,%2,%3}, {%4,%5,%6,%7}, {%8,%9}, {%0,%1,%2,%3};"
                 : "+f"(c[0]), "+f"(c[1]), "+f"(c[2]), "+f"(c[3])
                 : "r"(a[0]), "r"(a[1]), "r"(a[2]), "r"(a[3]), "r"(b[0]), "r"(b[1]));
}
__device__ __forceinline__ void split2(float v, __nv_bfloat16& h, __nv_bfloat16& l) {
    h = __float2bfloat16_rn(v);
    l = __float2bfloat16_rn(v - __bfloat162float(h));
}

// ============================================================================
// R4 mainloop (exact): block 128 x BN of C = A @ B^T, 256 threads,
// warps 4(m) x 2(n), warp tile 32x64 / 32x32.  k32 2-stage cp.async, SPAD=40.
// ============================================================================
#define SPAD 40

template<int BN>
__device__ __forceinline__ void gemm_tile(
    const __nv_bfloat16* __restrict__ Agh, const __nv_bfloat16* __restrict__ Agl, int lda,
    const __nv_bfloat16* __restrict__ Bgh, const __nv_bfloat16* __restrict__ Bgl, int ldb,
    int K, float (&acc)[2][BN / 16][4])
{
    extern __shared__ char smem_raw[];
    constexpr int NT   = BN / 16;
    constexpr int ASZ  = 128 * SPAD * 2;
    constexpr int BSZ  = BN  * SPAD * 2;
    constexpr int STAGE = 2 * ASZ + 2 * BSZ;

    const int tid  = threadIdx.x;
    const int lane = tid & 31;
    const int warp = tid >> 5;
    const int wm = (warp >> 1) * 32;
    const int wn = (warp & 1) * (BN / 2);

    const int lc = tid & 3;
    const int lr = tid >> 2;

    const uint32_t sbase = smem_u32(smem_raw);

    auto load_stage = [&](int s, int k0) {
        uint32_t base = sbase + s * STAGE;
#pragma unroll
        for (int rr = 0; rr < 2; rr++) {
            int row = lr + rr * 64;
            uint32_t doff = (uint32_t)(row * SPAD + lc * 8) * 2;
            cpasync16(base + doff,       Agh + (size_t)row * lda + k0 + lc * 8);
            cpasync16(base + ASZ + doff, Agl + (size_t)row * lda + k0 + lc * 8);
        }
#pragma unroll
        for (int rr = 0; rr < BN / 64; rr++) {
            int row = lr + rr * 64;
            uint32_t doff = (uint32_t)(row * SPAD + lc * 8) * 2;
            cpasync16(base + 2 * ASZ + doff,       Bgh + (size_t)row * ldb + k0 + lc * 8);
            cpasync16(base + 2 * ASZ + BSZ + doff, Bgl + (size_t)row * ldb + k0 + lc * 8);
        }
    };

    const int a_row = wm + (lane & 15);
    const int a_co  = (lane >> 4) << 3;
    const int g     = lane >> 3;
    const int b_rowbase = wn + (g >> 1) * 8 + (lane & 7);
    const int b_co  = (g & 1) * 8;

    int niter = K >> 5;
    load_stage(0, 0);
    asm volatile("cp.async.commit_group;");

    for (int it = 0; it < niter; it++) {
        int buf = it & 1;
        if (it + 1 < niter) {
            load_stage(buf ^ 1, (it + 1) * 32);
            asm volatile("cp.async.commit_group;");
            asm volatile("cp.async.wait_group 1;");
        } else {
            asm volatile("cp.async.wait_group 0;");
        }
        __syncthreads();

        uint32_t sb = sbase + buf * STAGE;
#pragma unroll
        for (int k16 = 0; k16 < 32; k16 += 16) {
            uint32_t ah[2][4], al[2][4];
#pragma unroll
            for (int mt = 0; mt < 2; mt++) {
                uint32_t addr = sb + (uint32_t)(((a_row + mt * 16) * SPAD + k16 + a_co) * 2);
                ldsm_x4(ah[mt], addr);
                ldsm_x4(al[mt], addr + ASZ);
            }
            uint32_t bhf[NT][2], blf[NT][2];
#pragma unroll
            for (int u = 0; u < NT; u += 2) {
                uint32_t addr = sb + 2 * ASZ +
                    (uint32_t)(((b_rowbase + u * 8) * SPAD + k16 + b_co) * 2);
                uint32_t t[4];
                ldsm_x4(t, addr);
                bhf[u][0] = t[0]; bhf[u][1] = t[1];
                bhf[u + 1][0] = t[2]; bhf[u + 1][1] = t[3];
                ldsm_x4(t, addr + BSZ);
                blf[u][0] = t[0]; blf[u][1] = t[1];
                blf[u + 1][0] = t[2]; blf[u + 1][1] = t[3];
            }
#pragma unroll
            for (int mt = 0; mt < 2; mt++) {
#pragma unroll
                for (int u = 0; u < NT; u++) {
                    mma16816(acc[mt][u], ah[mt], bhf[u]);
                    mma16816(acc[mt][u], ah[mt], blf[u]);
                    mma16816(acc[mt][u], al[mt], bhf[u]);
                }
            }
        }
        __syncthreads();
    }
}

// ============================================================================
// split: fp32 -> (hi, lo) bf16
// ============================================================================
__global__ __launch_bounds__(256)
void split_kernel(const float4* __restrict__ src, __nv_bfloat162* __restrict__ hi,
                  __nv_bfloat162* __restrict__ lo, int n4)
{
    int i = blockIdx.x * blockDim.x + threadIdx.x;
    if (i >= n4) return;
    float4 v = src[i];
    __nv_bfloat16 h0, h1, h2, h3, l0, l1, l2, l3;
    split2(v.x, h0, l0); split2(v.y, h1, l1);
    split2(v.z, h2, l2); split2(v.w, h3, l3);
    hi[2 * i]     = __nv_bfloat162(h0, h1);
    hi[2 * i + 1] = __nv_bfloat162(h2, h3);
    lo[2 * i]     = __nv_bfloat162(l0, l1);
    lo[2 * i + 1] = __nv_bfloat162(l2, l3);
}

// ============================================================================
// K1: QKV GEMM [4096 x 2304] (R4 exact).
// ============================================================================
__global__ __launch_bounds__(256)
void qkv_mma()
{
    float acc[2][8][4];
#pragma unroll
    for (int a = 0; a < 2; a++)
#pragma unroll
        for (int b = 0; b < 8; b++)
#pragma unroll
            for (int c = 0; c < 4; c++) acc[a][b][c] = 0.f;

    const int bx = blockIdx.x, by = blockIdx.y;
    gemm_tile<128>(g_xh + (size_t)(by * 128) * DIMC, g_xl + (size_t)(by * 128) * DIMC, DIMC,
                   g_wqh + (size_t)(bx * 128) * DIMC, g_wql + (size_t)(bx * 128) * DIMC, DIMC,
                   DIMC, acc);

    const int lane = threadIdx.x & 31, warp = threadIdx.x >> 5;
    const int wm = (warp >> 1) * 32, wn = (warp & 1) * 64;
    const int r = lane >> 2, cc = (lane & 3) * 2;

    const int which = bx / 6;           // 0:q 1:k 2:v
    __nv_bfloat16 *dh, *dl;
    float scl = 1.f;
    if (which == 0)      { dh = g_qh; dl = g_ql; scl = SCALE_F; }
    else if (which == 1) { dh = g_kh; dl = g_kl; }
    else                 { dh = g_vh; dl = g_vl; }
    const int cbase = bx * 128 - which * DIMC;

#pragma unroll
    for (int mt = 0; mt < 2; mt++) {
#pragma unroll
        for (int nt = 0; nt < 8; nt++) {
            int c = cbase + wn + nt * 8 + cc;
            int h = c >> 6, d = c & 63;
#pragma unroll
            for (int half = 0; half < 2; half++) {
                int m = by * 128 + wm + mt * 16 + r + half * 8;
                int b = m >> 10, qi = m & 1023;
                size_t idx = (((size_t)(b * NUM_HEADS + h) * SEQ) + qi) * HEAD_DIM + d;
                float v0 = acc[mt][nt][half * 2]     * scl;
                float v1 = acc[mt][nt][half * 2 + 1] * scl;
                __nv_bfloat16 h0, h1, l0, l1;
                split2(v0, h0, l0); split2(v1, h1, l1);
                *(__nv_bfloat162*)&dh[idx] = __nv_bfloat162(h0, h1);
                *(__nv_bfloat162*)&dl[idx] = __nv_bfloat162(l0, l1);
            }
        }
    }
}

// ============================================================================
// K2: transpose v -> vt (hi, lo)  (R4 exact)
// ============================================================================
__global__ __launch_bounds__(256)
void vt_kernel()
{
    __shared__ __nv_bfloat16 tile[32][33];
    const int bh = blockIdx.z, bx = blockIdx.x, by = blockIdx.y;
    const int tx = threadIdx.x, ty = threadIdx.y;
#pragma unroll
    for (int which = 0; which < 2; which++) {
        const __nv_bfloat16* src = (which ? g_vl : g_vh) + (size_t)bh * SEQ * HEAD_DIM;
        __nv_bfloat16* dst = (which ? g_vtl : g_vth) + (size_t)bh * HEAD_DIM * SEQ;
#pragma unroll
        for (int j = 0; j < 4; j++) {
            int s = bx * 32 + ty + j * 8;
            tile[ty + j * 8][tx] = src[(size_t)s * HEAD_DIM + by * 32 + tx];
        }
        __syncthreads();
#pragma unroll
        for (int j = 0; j < 4; j++) {
            int d = by * 32 + ty + j * 8;
            dst[(size_t)d * SEQ + bx * 32 + tx] = tile[tx][ty + j * 8];
        }
        __syncthreads();
    }
}

// ============================================================================
// K3: FUSED S + softmax.  One block per (128-row strip by, head bh).
// Pass 1: loop 8 column tiles (R4 mainloop), write logits, track row maxes.
// Pass 2: L2-hot strip re-read -> row sums -> normalize -> fp32 attn + ph/pl.
// ============================================================================
__global__ __launch_bounds__(256)
void s_softmax_mma(float* attn_out)
{
    float* attn = attn_out ? attn_out : g_attn;
    const int by = blockIdx.x, bh = blockIdx.y;
    const int tid = threadIdx.x;
    const int lane = tid & 31, warp = tid >> 5;
    const int wm = (warp >> 1) * 32, wn = (warp & 1) * 64;
    const int r = lane >> 2, cc = (lane & 3) * 2;

    __shared__ float s_m2[128][2];
    __shared__ float s_row[128];     // row max, then reused pattern below
    __shared__ float s_inv[128];

    const size_t hb = (size_t)bh * SEQ * HEAD_DIM;
    float* C = attn + (size_t)bh * SEQ * SEQ + (size_t)(by * 128) * SEQ;

    float m_run[2][2];
#pragma unroll
    for (int a = 0; a < 2; a++) { m_run[a][0] = -1e30f; m_run[a][1] = -1e30f; }

    for (int bx = 0; bx < 8; bx++) {
        float acc[2][8][4];
#pragma unroll
        for (int a = 0; a < 2; a++)
#pragma unroll
            for (int b = 0; b < 8; b++)
#pragma unroll
                for (int c = 0; c < 4; c++) acc[a][b][c] = 0.f;

        gemm_tile<128>(g_qh + hb + (size_t)(by * 128) * HEAD_DIM,
                       g_ql + hb + (size_t)(by * 128) * HEAD_DIM, HEAD_DIM,
                       g_kh + hb + (size_t)(bx * 128) * HEAD_DIM,
                       g_kl + hb + (size_t)(bx * 128) * HEAD_DIM, HEAD_DIM,
                       HEAD_DIM, acc);

        // write logits + update per-thread row maxes
#pragma unroll
        for (int mt = 0; mt < 2; mt++) {
#pragma unroll
            for (int half = 0; half < 2; half++) {
                int m = wm + mt * 16 + r + half * 8;
                float mx = m_run[mt][half];
#pragma unroll
                for (int nt = 0; nt < 8; nt++) {
                    float v0 = acc[mt][nt][half * 2];
                    float v1 = acc[mt][nt][half * 2 + 1];
                    int n = bx * 128 + wn + nt * 8 + cc;
                    *(float2*)&C[(size_t)m * SEQ + n] = make_float2(v0, v1);
                    mx = fmaxf(mx, fmaxf(v0, v1));
                }
                m_run[mt][half] = mx;
            }
        }
    }

    // reduce maxes: quad (cols within warp segment), then across warp pair
#pragma unroll
    for (int mt = 0; mt < 2; mt++)
#pragma unroll
        for (int half = 0; half < 2; half++) {
            float mx = m_run[mt][half];
            mx = fmaxf(mx, __shfl_xor_sync(0xFFFFFFFFu, mx, 1));
            mx = fmaxf(mx, __shfl_xor_sync(0xFFFFFFFFu, mx, 2));
            if ((lane & 3) == 0)
                s_m2[wm + mt * 16 + r + half * 8][warp & 1] = mx;
        }
    __syncthreads();
    if (tid < 128) s_row[tid] = fmaxf(s_m2[tid][0], s_m2[tid][1]);
    __syncthreads();

    // pass 2a: row sums (warp w handles rows w*16..w*16+15, coalesced)
#pragma unroll 1
    for (int rr = 0; rr < 16; rr++) {
        int row = warp * 16 + rr;
        const float rm = s_row[row];
        const float4* rp = (const float4*)(C + (size_t)row * SEQ);
        float sum = 0.f;
#pragma unroll
        for (int i = 0; i < 8; i++) {
            float4 v = rp[i * 32 + lane];
            sum += __expf(v.x - rm) + __expf(v.y - rm)
                 + __expf(v.z - rm) + __expf(v.w - rm);
        }
#pragma unroll
        for (int o = 16; o > 0; o >>= 1) sum += __shfl_xor_sync(0xFFFFFFFFu, sum, o);
        if (lane == 0) s_inv[row] = 1.0f / sum;
    }
    __syncthreads();

    // pass 2b: normalize -> fp32 attn (in place) + bf16 ph/pl
    const size_t pstrip = (size_t)bh * SEQ * SEQ + (size_t)(by * 128) * SEQ;
#pragma unroll 1
    for (int rr = 0; rr < 16; rr++) {
        int row = warp * 16 + rr;
        const float rm = s_row[row];
        const float inv = s_inv[row];
        float4* rp = (float4*)(C + (size_t)row * SEQ);
        const size_t prow = pstrip + (size_t)row * SEQ;
#pragma unroll
        for (int i = 0; i < 8; i++) {
            int col = (i * 32 + lane) * 4;
            float4 v = rp[i * 32 + lane];
            v.x = __expf(v.x - rm) * inv;
            v.y = __expf(v.y - rm) * inv;
            v.z = __expf(v.z - rm) * inv;
            v.w = __expf(v.w - rm) * inv;
            rp[i * 32 + lane] = v;
            __nv_bfloat16 h0, h1, h2, h3, l0, l1, l2, l3;
            split2(v.x, h0, l0); split2(v.y, h1, l1);
            split2(v.z, h2, l2); split2(v.w, h3, l3);
            *(__nv_bfloat162*)&g_ph[prow + col]     = __nv_bfloat162(h0, h1);
            *(__nv_bfloat162*)&g_ph[prow + col + 2] = __nv_bfloat162(h2, h3);
            *(__nv_bfloat162*)&g_pl[prow + col]     = __nv_bfloat162(l0, l1);
            *(__nv_bfloat162*)&g_pl[prow + col + 2] = __nv_bfloat162(l2, l3);
        }
    }
}

// ============================================================================
// K5: O = P @ vt^T per (b,h) (R4 exact).  128x64, K=1024.
// ============================================================================
__global__ __launch_bounds__(256)
void o_mma()
{
    float acc[2][4][4];
#pragma unroll
    for (int a = 0; a < 2; a++)
#pragma unroll
        for (int b = 0; b < 4; b++)
#pragma unroll
            for (int c = 0; c < 4; c++) acc[a][b][c] = 0.f;

    const int bh = blockIdx.y, bx = blockIdx.x;
    const int b = bh / NUM_HEADS, h = bh - b * NUM_HEADS;
    gemm_tile<64>(g_ph + (size_t)bh * SEQ * SEQ + (size_t)(bx * 128) * SEQ,
                  g_pl + (size_t)bh * SEQ * SEQ + (size_t)(bx * 128) * SEQ, SEQ,
                  g_vth + (size_t)bh * HEAD_DIM * SEQ,
                  g_vtl + (size_t)bh * HEAD_DIM * SEQ, SEQ,
                  SEQ, acc);

    const int lane = threadIdx.x & 31, warp = threadIdx.x >> 5;
    const int wm = (warp >> 1) * 32, wn = (warp & 1) * 32;
    const int r = lane >> 2, cc = (lane & 3) * 2;

#pragma unroll
    for (int mt = 0; mt < 2; mt++) {
#pragma unroll
        for (int nt = 0; nt < 4; nt++) {
            int d = wn + nt * 8 + cc;
#pragma unroll
            for (int half = 0; half < 2; half++) {
                int mseq = bx * 128 + wm + mt * 16 + r + half * 8;
                size_t idx = ((size_t)b * SEQ + mseq) * DIMC + h * HEAD_DIM + d;
                float v0 = acc[mt][nt][half * 2];
                float v1 = acc[mt][nt][half * 2 + 1];
                __nv_bfloat16 h0, h1, l0, l1;
                split2(v0, h0, l0); split2(v1, h1, l1);
                *(__nv_bfloat162*)&g_oh[idx] = __nv_bfloat162(h0, h1);
                *(__nv_bfloat162*)&g_ol[idx] = __nv_bfloat162(l0, l1);
            }
        }
    }
}

// ============================================================================
// K6: out = O @ w_proj^T + bias (R4 exact).
// ============================================================================
__global__ __launch_bounds__(256)
void proj_mma(const float* __restrict__ bias, float* out_ptr)
{
    float* outp = out_ptr ? out_ptr : g_outs;
    float acc[2][8][4];
#pragma unroll
    for (int a = 0; a < 2; a++)
#pragma unroll
        for (int b = 0; b < 8; b++)
#pragma unroll
            for (int c = 0; c < 4; c++) acc[a][b][c] = 0.f;

    const int bx = blockIdx.x, by = blockIdx.y;
    gemm_tile<128>(g_oh + (size_t)(by * 128) * DIMC, g_ol + (size_t)(by * 128) * DIMC, DIMC,
                   g_wph + (size_t)(bx * 128) * DIMC, g_wpl + (size_t)(bx * 128) * DIMC, DIMC,
                   DIMC, acc);

    const int lane = threadIdx.x & 31, warp = threadIdx.x >> 5;
    const int wm = (warp >> 1) * 32, wn = (warp & 1) * 64;
    const int r = lane >> 2, cc = (lane & 3) * 2;

#pragma unroll
    for (int mt = 0; mt < 2; mt++) {
#pragma unroll
        for (int nt = 0; nt < 8; nt++) {
            int n = bx * 128 + wn + nt * 8 + cc;
            float b0 = bias[n], b1 = bias[n + 1];
#pragma unroll
            for (int half = 0; half < 2; half++) {
                int m = by * 128 + wm + mt * 16 + r + half * 8;
                *(float2*)&outp[(size_t)m * DIMC + n] =
                    make_float2(acc[mt][nt][half * 2] + b0, acc[mt][nt][half * 2 + 1] + b1);
            }
        }
    }
}

// ============================================================================
// launch (serial, default stream — no streams/events)
// ============================================================================
extern "C" void kernel_launch(void* const* d_in, const int* in_sizes, int n_in,
                              void* d_out, int out_size)
{
    const float* x      = (const float*)d_in[0];
    const float* w_qkv  = (const float*)d_in[1];
    const float* w_proj = (const float*)d_in[2];
    const float* b_proj = (const float*)d_in[3];
    (void)in_sizes; (void)n_in;

    float* dof = (float*)d_out;
    float* out_ptr  = nullptr;
    float* attn_ptr = nullptr;
    size_t osz = (size_t)out_size;
    if (osz >= OUT_ELEMS + ATTN_ELEMS) { out_ptr = dof; attn_ptr = dof + OUT_ELEMS; }
    else if (osz == ATTN_ELEMS)        { attn_ptr = dof; }
    else                               { out_ptr = dof; }

    const int SM_BIG = 2 * (2 * 128 * SPAD * 2 + 2 * 128 * SPAD * 2);  // 81920
    const int SM_O   = 2 * (2 * 128 * SPAD * 2 + 2 * 64  * SPAD * 2);  // 61440
    cudaFuncSetAttribute(qkv_mma,       cudaFuncAttributeMaxDynamicSharedMemorySize, SM_BIG);
    cudaFuncSetAttribute(s_softmax_mma, cudaFuncAttributeMaxDynamicSharedMemorySize, SM_BIG);
    cudaFuncSetAttribute(proj_mma,      cudaFuncAttributeMaxDynamicSharedMemorySize, SM_BIG);
    cudaFuncSetAttribute(o_mma,         cudaFuncAttributeMaxDynamicSharedMemorySize, SM_O);

    void *p_xh, *p_xl, *p_wqh, *p_wql, *p_wph, *p_wpl;
    cudaGetSymbolAddress(&p_xh, g_xh);   cudaGetSymbolAddress(&p_xl, g_xl);
    cudaGetSymbolAddress(&p_wqh, g_wqh); cudaGetSymbolAddress(&p_wql, g_wql);
    cudaGetSymbolAddress(&p_wph, g_wph); cudaGetSymbolAddress(&p_wpl, g_wpl);

    dim3 blk(256);

    { int n4 = M_TOK * DIMC / 4;
      split_kernel<<<(n4 + 255) / 256, blk>>>((const float4*)x,
          (__nv_bfloat162*)p_xh, (__nv_bfloat162*)p_xl, n4); }
    { int n4 = QKV_N * DIMC / 4;
      split_kernel<<<(n4 + 255) / 256, blk>>>((const float4*)w_qkv,
          (__nv_bfloat162*)p_wqh, (__nv_bfloat162*)p_wql, n4); }
    { int n4 = DIMC * DIMC / 4;
      split_kernel<<<(n4 + 255) / 256, blk>>>((const float4*)w_proj,
          (__nv_bfloat162*)p_wph, (__nv_bfloat162*)p_wpl, n4); }

    qkv_mma<<<dim3(QKV_N / 128, M_TOK / 128), blk, SM_BIG>>>();

    vt_kernel<<<dim3(SEQ / 32, HEAD_DIM / 32, BH), dim3(32, 8)>>>();

    // fused S + softmax: one block per (row strip, head)
    s_softmax_mma<<<dim3(SEQ / 128, BH), blk, SM_BIG>>>(attn_ptr);

    o_mma<<<dim3(SEQ / 128, BH), blk, SM_O>>>();

    proj_mma<<<dim3(DIMC / 128, M_TOK / 128), blk, SM_BIG>>>(b_proj, out_ptr);
}

// round 13
// speedup vs baseline: 1.3253x; 1.3253x over previous
#include <cuda_runtime.h>
#include <cuda_bf16.h>
#include <cstdint>

// ============================================================================
// Attention_84129819394524 — R4 configuration (proven 483us) with three
// bounded micro-optimizations: single fused split kernel, __expf softmax,
// packed 8B ph/pl stores. All GEMM kernels byte-identical to R4.
// ============================================================================

#define NUM_HEADS 12
#define HEAD_DIM  64
#define DIMC      768
#define BATCH     4
#define SEQ       1024
#define SCALE_F   0.125f

#define M_TOK   (BATCH * SEQ)          // 4096
#define QKV_N   (3 * DIMC)             // 2304
#define BH      (BATCH * NUM_HEADS)    // 48

#define OUT_ELEMS  ((size_t)M_TOK * DIMC)
#define ATTN_ELEMS ((size_t)BH * SEQ * SEQ)

// ---------------- device scratch (allocation-free) ----------------
__device__ __align__(16) __nv_bfloat16 g_xh [M_TOK * DIMC];
__device__ __align__(16) __nv_bfloat16 g_xl [M_TOK * DIMC];
__device__ __align__(16) __nv_bfloat16 g_wqh[QKV_N * DIMC];
__device__ __align__(16) __nv_bfloat16 g_wql[QKV_N * DIMC];
__device__ __align__(16) __nv_bfloat16 g_wph[DIMC * DIMC];
__device__ __align__(16) __nv_bfloat16 g_wpl[DIMC * DIMC];
__device__ __align__(16) __nv_bfloat16 g_qh [BH * SEQ * HEAD_DIM];
__device__ __align__(16) __nv_bfloat16 g_ql [BH * SEQ * HEAD_DIM];
__device__ __align__(16) __nv_bfloat16 g_kh [BH * SEQ * HEAD_DIM];
__device__ __align__(16) __nv_bfloat16 g_kl [BH * SEQ * HEAD_DIM];
__device__ __align__(16) __nv_bfloat16 g_vh [BH * SEQ * HEAD_DIM];
__device__ __align__(16) __nv_bfloat16 g_vl [BH * SEQ * HEAD_DIM];
__device__ __align__(16) __nv_bfloat16 g_vth[BH * HEAD_DIM * SEQ];
__device__ __align__(16) __nv_bfloat16 g_vtl[BH * HEAD_DIM * SEQ];
__device__ __align__(16) __nv_bfloat16 g_ph [BH * SEQ * SEQ];
__device__ __align__(16) __nv_bfloat16 g_pl [BH * SEQ * SEQ];
__device__ __align__(16) __nv_bfloat16 g_oh [M_TOK * DIMC];
__device__ __align__(16) __nv_bfloat16 g_ol [M_TOK * DIMC];
__device__ __align__(256) float g_attn[ATTN_ELEMS];
__device__ __align__(256) float g_outs[OUT_ELEMS];

// ---------------- helpers ----------------
__device__ __forceinline__ uint32_t smem_u32(const void* p) {
    return (uint32_t)__cvta_generic_to_shared(p);
}
__device__ __forceinline__ void cpasync16(uint32_t dst, const void* src) {
    asm volatile("cp.async.cg.shared.global [%0], [%1], 16;" :: "r"(dst), "l"(src));
}
__device__ __forceinline__ void ldsm_x4(uint32_t* r, uint32_t addr) {
    asm volatile("ldmatrix.sync.aligned.m8n8.x4.shared.b16 {%0,%1,%2,%3}, [%4];"
                 : "=r"(r[0]), "=r"(r[1]), "=r"(r[2]), "=r"(r[3]) : "r"(addr));
}
__device__ __forceinline__ void mma16816(float* c, const uint32_t* a, const uint32_t* b) {
    asm volatile("mma.sync.aligned.m16n8k16.row.col.f32.bf16.bf16.f32 "
                 "{%0,%1,%2,%3}, {%4,%5,%6,%7}, {%8,%9}, {%0,%1,%2,%3};"
                 : "+f"(c[0]), "+f"(c[1]), "+f"(c[2]), "+f"(c[3])
                 : "r"(a[0]), "r"(a[1]), "r"(a[2]), "r"(a[3]), "r"(b[0]), "r"(b[1]));
}
__device__ __forceinline__ void split2(float v, __nv_bfloat16& h, __nv_bfloat16& l) {
    h = __float2bfloat16_rn(v);
    l = __float2bfloat16_rn(v - __bfloat162float(h));
}
__device__ __forceinline__ uint32_t pack_bf2(__nv_bfloat16 a, __nv_bfloat16 b) {
    __nv_bfloat162 t(a, b);
    return *(uint32_t*)&t;
}

// ============================================================================
// R4 mainloop (exact): block 128 x BN of C = A @ B^T, 256 threads,
// warps 4(m) x 2(n), warp tile 32x64 / 32x32.  k32 2-stage cp.async, SPAD=40.
// ============================================================================
#define SPAD 40

template<int BN>
__device__ __forceinline__ void gemm_tile(
    const __nv_bfloat16* __restrict__ Agh, const __nv_bfloat16* __restrict__ Agl, int lda,
    const __nv_bfloat16* __restrict__ Bgh, const __nv_bfloat16* __restrict__ Bgl, int ldb,
    int K, float (&acc)[2][BN / 16][4])
{
    extern __shared__ char smem_raw[];
    constexpr int NT   = BN / 16;
    constexpr int ASZ  = 128 * SPAD * 2;
    constexpr int BSZ  = BN  * SPAD * 2;
    constexpr int STAGE = 2 * ASZ + 2 * BSZ;

    const int tid  = threadIdx.x;
    const int lane = tid & 31;
    const int warp = tid >> 5;
    const int wm = (warp >> 1) * 32;
    const int wn = (warp & 1) * (BN / 2);

    const int lc = tid & 3;
    const int lr = tid >> 2;

    const uint32_t sbase = smem_u32(smem_raw);

    auto load_stage = [&](int s, int k0) {
        uint32_t base = sbase + s * STAGE;
#pragma unroll
        for (int rr = 0; rr < 2; rr++) {
            int row = lr + rr * 64;
            uint32_t doff = (uint32_t)(row * SPAD + lc * 8) * 2;
            cpasync16(base + doff,       Agh + (size_t)row * lda + k0 + lc * 8);
            cpasync16(base + ASZ + doff, Agl + (size_t)row * lda + k0 + lc * 8);
        }
#pragma unroll
        for (int rr = 0; rr < BN / 64; rr++) {
            int row = lr + rr * 64;
            uint32_t doff = (uint32_t)(row * SPAD + lc * 8) * 2;
            cpasync16(base + 2 * ASZ + doff,       Bgh + (size_t)row * ldb + k0 + lc * 8);
            cpasync16(base + 2 * ASZ + BSZ + doff, Bgl + (size_t)row * ldb + k0 + lc * 8);
        }
    };

    const int a_row = wm + (lane & 15);
    const int a_co  = (lane >> 4) << 3;
    const int g     = lane >> 3;
    const int b_rowbase = wn + (g >> 1) * 8 + (lane & 7);
    const int b_co  = (g & 1) * 8;

    int niter = K >> 5;
    load_stage(0, 0);
    asm volatile("cp.async.commit_group;");

    for (int it = 0; it < niter; it++) {
        int buf = it & 1;
        if (it + 1 < niter) {
            load_stage(buf ^ 1, (it + 1) * 32);
            asm volatile("cp.async.commit_group;");
            asm volatile("cp.async.wait_group 1;");
        } else {
            asm volatile("cp.async.wait_group 0;");
        }
        __syncthreads();

        uint32_t sb = sbase + buf * STAGE;
#pragma unroll
        for (int k16 = 0; k16 < 32; k16 += 16) {
            uint32_t ah[2][4], al[2][4];
#pragma unroll
            for (int mt = 0; mt < 2; mt++) {
                uint32_t addr = sb + (uint32_t)(((a_row + mt * 16) * SPAD + k16 + a_co) * 2);
                ldsm_x4(ah[mt], addr);
                ldsm_x4(al[mt], addr + ASZ);
            }
            uint32_t bhf[NT][2], blf[NT][2];
#pragma unroll
            for (int u = 0; u < NT; u += 2) {
                uint32_t addr = sb + 2 * ASZ +
                    (uint32_t)(((b_rowbase + u * 8) * SPAD + k16 + b_co) * 2);
                uint32_t t[4];
                ldsm_x4(t, addr);
                bhf[u][0] = t[0]; bhf[u][1] = t[1];
                bhf[u + 1][0] = t[2]; bhf[u + 1][1] = t[3];
                ldsm_x4(t, addr + BSZ);
                blf[u][0] = t[0]; blf[u][1] = t[1];
                blf[u + 1][0] = t[2]; blf[u + 1][1] = t[3];
            }
#pragma unroll
            for (int mt = 0; mt < 2; mt++) {
#pragma unroll
                for (int u = 0; u < NT; u++) {
                    mma16816(acc[mt][u], ah[mt], bhf[u]);
                    mma16816(acc[mt][u], ah[mt], blf[u]);
                    mma16816(acc[mt][u], al[mt], bhf[u]);
                }
            }
        }
        __syncthreads();
    }
}

// ============================================================================
// Fused split: one grid handles x, w_qkv, w_proj  (fp32 -> hi/lo bf16)
// ============================================================================
#define N4_X  (M_TOK * DIMC / 4)     // 786432
#define N4_WQ (QKV_N * DIMC / 4)     // 442368
#define N4_WP (DIMC * DIMC / 4)      // 147456
#define N4_TOTAL (N4_X + N4_WQ + N4_WP)

__global__ __launch_bounds__(256)
void split_all_kernel(const float4* __restrict__ x, const float4* __restrict__ wq,
                      const float4* __restrict__ wp)
{
    int i = blockIdx.x * blockDim.x + threadIdx.x;
    if (i >= N4_TOTAL) return;

    const float4* src;
    __nv_bfloat162 *hi, *lo;
    int j;
    if (i < N4_X) {
        src = x;  hi = (__nv_bfloat162*)g_xh;  lo = (__nv_bfloat162*)g_xl;  j = i;
    } else if (i < N4_X + N4_WQ) {
        src = wq; hi = (__nv_bfloat162*)g_wqh; lo = (__nv_bfloat162*)g_wql; j = i - N4_X;
    } else {
        src = wp; hi = (__nv_bfloat162*)g_wph; lo = (__nv_bfloat162*)g_wpl; j = i - N4_X - N4_WQ;
    }

    float4 v = src[j];
    __nv_bfloat16 h0, h1, h2, h3, l0, l1, l2, l3;
    split2(v.x, h0, l0); split2(v.y, h1, l1);
    split2(v.z, h2, l2); split2(v.w, h3, l3);
    hi[2 * j]     = __nv_bfloat162(h0, h1);
    hi[2 * j + 1] = __nv_bfloat162(h2, h3);
    lo[2 * j]     = __nv_bfloat162(l0, l1);
    lo[2 * j + 1] = __nv_bfloat162(l2, l3);
}

// ============================================================================
// K1: QKV GEMM [4096 x 2304] (R4 exact).
// ============================================================================
__global__ __launch_bounds__(256)
void qkv_mma()
{
    float acc[2][8][4];
#pragma unroll
    for (int a = 0; a < 2; a++)
#pragma unroll
        for (int b = 0; b < 8; b++)
#pragma unroll
            for (int c = 0; c < 4; c++) acc[a][b][c] = 0.f;

    const int bx = blockIdx.x, by = blockIdx.y;
    gemm_tile<128>(g_xh + (size_t)(by * 128) * DIMC, g_xl + (size_t)(by * 128) * DIMC, DIMC,
                   g_wqh + (size_t)(bx * 128) * DIMC, g_wql + (size_t)(bx * 128) * DIMC, DIMC,
                   DIMC, acc);

    const int lane = threadIdx.x & 31, warp = threadIdx.x >> 5;
    const int wm = (warp >> 1) * 32, wn = (warp & 1) * 64;
    const int r = lane >> 2, cc = (lane & 3) * 2;

    const int which = bx / 6;           // 0:q 1:k 2:v
    __nv_bfloat16 *dh, *dl;
    float scl = 1.f;
    if (which == 0)      { dh = g_qh; dl = g_ql; scl = SCALE_F; }
    else if (which == 1) { dh = g_kh; dl = g_kl; }
    else                 { dh = g_vh; dl = g_vl; }
    const int cbase = bx * 128 - which * DIMC;

#pragma unroll
    for (int mt = 0; mt < 2; mt++) {
#pragma unroll
        for (int nt = 0; nt < 8; nt++) {
            int c = cbase + wn + nt * 8 + cc;
            int h = c >> 6, d = c & 63;
#pragma unroll
            for (int half = 0; half < 2; half++) {
                int m = by * 128 + wm + mt * 16 + r + half * 8;
                int b = m >> 10, qi = m & 1023;
                size_t idx = (((size_t)(b * NUM_HEADS + h) * SEQ) + qi) * HEAD_DIM + d;
                float v0 = acc[mt][nt][half * 2]     * scl;
                float v1 = acc[mt][nt][half * 2 + 1] * scl;
                __nv_bfloat16 h0, h1, l0, l1;
                split2(v0, h0, l0); split2(v1, h1, l1);
                *(__nv_bfloat162*)&dh[idx] = __nv_bfloat162(h0, h1);
                *(__nv_bfloat162*)&dl[idx] = __nv_bfloat162(l0, l1);
            }
        }
    }
}

// ============================================================================
// K2: transpose v -> vt (hi, lo)  (R4 exact)
// ============================================================================
__global__ __launch_bounds__(256)
void vt_kernel()
{
    __shared__ __nv_bfloat16 tile[32][33];
    const int bh = blockIdx.z, bx = blockIdx.x, by = blockIdx.y;
    const int tx = threadIdx.x, ty = threadIdx.y;
#pragma unroll
    for (int which = 0; which < 2; which++) {
        const __nv_bfloat16* src = (which ? g_vl : g_vh) + (size_t)bh * SEQ * HEAD_DIM;
        __nv_bfloat16* dst = (which ? g_vtl : g_vth) + (size_t)bh * HEAD_DIM * SEQ;
#pragma unroll
        for (int j = 0; j < 4; j++) {
            int s = bx * 32 + ty + j * 8;
            tile[ty + j * 8][tx] = src[(size_t)s * HEAD_DIM + by * 32 + tx];
        }
        __syncthreads();
#pragma unroll
        for (int j = 0; j < 4; j++) {
            int d = by * 32 + ty + j * 8;
            dst[(size_t)d * SEQ + bx * 32 + tx] = tile[tx][ty + j * 8];
        }
        __syncthreads();
    }
}

// ============================================================================
// K3: S = q @ k^T per (b,h) (R4 exact).
// ============================================================================
__global__ __launch_bounds__(256)
void s_mma(float* attn_out)
{
    float* attn = attn_out ? attn_out : g_attn;
    float acc[2][8][4];
#pragma unroll
    for (int a = 0; a < 2; a++)
#pragma unroll
        for (int b = 0; b < 8; b++)
#pragma unroll
            for (int c = 0; c < 4; c++) acc[a][b][c] = 0.f;

    const int bh = blockIdx.z, bx = blockIdx.x, by = blockIdx.y;
    const size_t hb = (size_t)bh * SEQ * HEAD_DIM;
    gemm_tile<128>(g_qh + hb + (size_t)(by * 128) * HEAD_DIM,
                   g_ql + hb + (size_t)(by * 128) * HEAD_DIM, HEAD_DIM,
                   g_kh + hb + (size_t)(bx * 128) * HEAD_DIM,
                   g_kl + hb + (size_t)(bx * 128) * HEAD_DIM, HEAD_DIM,
                   HEAD_DIM, acc);

    const int lane = threadIdx.x & 31, warp = threadIdx.x >> 5;
    const int wm = (warp >> 1) * 32, wn = (warp & 1) * 64;
    const int r = lane >> 2, cc = (lane & 3) * 2;
    float* C = attn + (size_t)bh * SEQ * SEQ;

#pragma unroll
    for (int mt = 0; mt < 2; mt++) {
#pragma unroll
        for (int nt = 0; nt < 8; nt++) {
            int n = bx * 128 + wn + nt * 8 + cc;
#pragma unroll
            for (int half = 0; half < 2; half++) {
                int m = by * 128 + wm + mt * 16 + r + half * 8;
                *(float2*)&C[(size_t)m * SEQ + n] =
                    make_float2(acc[mt][nt][half * 2], acc[mt][nt][half * 2 + 1]);
            }
        }
    }
}

// ============================================================================
// K4: row softmax in place + emit P hi/lo (fast __expf, packed 8B stores)
// ============================================================================
__global__ __launch_bounds__(256)
void softmax_kernel(float* attn_out)
{
    float* attn = attn_out ? attn_out : g_attn;
    float* p = attn + (size_t)blockIdx.x * SEQ;
    const size_t pbase = (size_t)blockIdx.x * SEQ;
    const int tid = threadIdx.x;
    __shared__ float red_max[8];
    __shared__ float red_sum[8];

    float4 v = reinterpret_cast<float4*>(p)[tid];
    float m = fmaxf(fmaxf(v.x, v.y), fmaxf(v.z, v.w));
#pragma unroll
    for (int o = 16; o > 0; o >>= 1) m = fmaxf(m, __shfl_xor_sync(0xFFFFFFFFu, m, o));
    if ((tid & 31) == 0) red_max[tid >> 5] = m;
    __syncthreads();
    if (tid == 0) {
        float t = red_max[0];
#pragma unroll
        for (int i = 1; i < 8; i++) t = fmaxf(t, red_max[i]);
        red_max[0] = t;
    }
    __syncthreads();
    const float rmax = red_max[0];

    v.x = __expf(v.x - rmax); v.y = __expf(v.y - rmax);
    v.z = __expf(v.z - rmax); v.w = __expf(v.w - rmax);
    float s = v.x + v.y + v.z + v.w;
#pragma unroll
    for (int o = 16; o > 0; o >>= 1) s += __shfl_xor_sync(0xFFFFFFFFu, s, o);
    if ((tid & 31) == 0) red_sum[tid >> 5] = s;
    __syncthreads();
    if (tid == 0) {
        float t = 0.f;
#pragma unroll
        for (int i = 0; i < 8; i++) t += red_sum[i];
        red_sum[0] = t;
    }
    __syncthreads();
    const float inv = 1.0f / red_sum[0];
    v.x *= inv; v.y *= inv; v.z *= inv; v.w *= inv;
    reinterpret_cast<float4*>(p)[tid] = v;

    __nv_bfloat16 h0, h1, h2, h3, l0, l1, l2, l3;
    split2(v.x, h0, l0); split2(v.y, h1, l1);
    split2(v.z, h2, l2); split2(v.w, h3, l3);
    size_t idx = pbase + tid * 4;
    *(uint2*)&g_ph[idx] = make_uint2(pack_bf2(h0, h1), pack_bf2(h2, h3));
    *(uint2*)&g_pl[idx] = make_uint2(pack_bf2(l0, l1), pack_bf2(l2, l3));
}

// ============================================================================
// K5: O = P @ vt^T per (b,h) (R4 exact).  128x64, K=1024.
// ============================================================================
__global__ __launch_bounds__(256)
void o_mma()
{
    float acc[2][4][4];
#pragma unroll
    for (int a = 0; a < 2; a++)
#pragma unroll
        for (int b = 0; b < 4; b++)
#pragma unroll
            for (int c = 0; c < 4; c++) acc[a][b][c] = 0.f;

    const int bh = blockIdx.y, bx = blockIdx.x;
    const int b = bh / NUM_HEADS, h = bh - b * NUM_HEADS;
    gemm_tile<64>(g_ph + (size_t)bh * SEQ * SEQ + (size_t)(bx * 128) * SEQ,
                  g_pl + (size_t)bh * SEQ * SEQ + (size_t)(bx * 128) * SEQ, SEQ,
                  g_vth + (size_t)bh * HEAD_DIM * SEQ,
                  g_vtl + (size_t)bh * HEAD_DIM * SEQ, SEQ,
                  SEQ, acc);

    const int lane = threadIdx.x & 31, warp = threadIdx.x >> 5;
    const int wm = (warp >> 1) * 32, wn = (warp & 1) * 32;
    const int r = lane >> 2, cc = (lane & 3) * 2;

#pragma unroll
    for (int mt = 0; mt < 2; mt++) {
#pragma unroll
        for (int nt = 0; nt < 4; nt++) {
            int d = wn + nt * 8 + cc;
#pragma unroll
            for (int half = 0; half < 2; half++) {
                int mseq = bx * 128 + wm + mt * 16 + r + half * 8;
                size_t idx = ((size_t)b * SEQ + mseq) * DIMC + h * HEAD_DIM + d;
                float v0 = acc[mt][nt][half * 2];
                float v1 = acc[mt][nt][half * 2 + 1];
                __nv_bfloat16 h0, h1, l0, l1;
                split2(v0, h0, l0); split2(v1, h1, l1);
                *(__nv_bfloat162*)&g_oh[idx] = __nv_bfloat162(h0, h1);
                *(__nv_bfloat162*)&g_ol[idx] = __nv_bfloat162(l0, l1);
            }
        }
    }
}

// ============================================================================
// K6: out = O @ w_proj^T + bias (R4 exact).
// ============================================================================
__global__ __launch_bounds__(256)
void proj_mma(const float* __restrict__ bias, float* out_ptr)
{
    float* outp = out_ptr ? out_ptr : g_outs;
    float acc[2][8][4];
#pragma unroll
    for (int a = 0; a < 2; a++)
#pragma unroll
        for (int b = 0; b < 8; b++)
#pragma unroll
            for (int c = 0; c < 4; c++) acc[a][b][c] = 0.f;

    const int bx = blockIdx.x, by = blockIdx.y;
    gemm_tile<128>(g_oh + (size_t)(by * 128) * DIMC, g_ol + (size_t)(by * 128) * DIMC, DIMC,
                   g_wph + (size_t)(bx * 128) * DIMC, g_wpl + (size_t)(bx * 128) * DIMC, DIMC,
                   DIMC, acc);

    const int lane = threadIdx.x & 31, warp = threadIdx.x >> 5;
    const int wm = (warp >> 1) * 32, wn = (warp & 1) * 64;
    const int r = lane >> 2, cc = (lane & 3) * 2;

#pragma unroll
    for (int mt = 0; mt < 2; mt++) {
#pragma unroll
        for (int nt = 0; nt < 8; nt++) {
            int n = bx * 128 + wn + nt * 8 + cc;
            float b0 = bias[n], b1 = bias[n + 1];
#pragma unroll
            for (int half = 0; half < 2; half++) {
                int m = by * 128 + wm + mt * 16 + r + half * 8;
                *(float2*)&outp[(size_t)m * DIMC + n] =
                    make_float2(acc[mt][nt][half * 2] + b0, acc[mt][nt][half * 2 + 1] + b1);
            }
        }
    }
}

// ============================================================================
// launch (serial, default stream)
// ============================================================================
extern "C" void kernel_launch(void* const* d_in, const int* in_sizes, int n_in,
                              void* d_out, int out_size)
{
    const float* x      = (const float*)d_in[0];
    const float* w_qkv  = (const float*)d_in[1];
    const float* w_proj = (const float*)d_in[2];
    const float* b_proj = (const float*)d_in[3];
    (void)in_sizes; (void)n_in;

    float* dof = (float*)d_out;
    float* out_ptr  = nullptr;
    float* attn_ptr = nullptr;
    size_t osz = (size_t)out_size;
    if (osz >= OUT_ELEMS + ATTN_ELEMS) { out_ptr = dof; attn_ptr = dof + OUT_ELEMS; }
    else if (osz == ATTN_ELEMS)        { attn_ptr = dof; }
    else                               { out_ptr = dof; }

    const int SM_BIG = 2 * (2 * 128 * SPAD * 2 + 2 * 128 * SPAD * 2);  // 81920
    const int SM_O   = 2 * (2 * 128 * SPAD * 2 + 2 * 64  * SPAD * 2);  // 61440
    cudaFuncSetAttribute(qkv_mma,  cudaFuncAttributeMaxDynamicSharedMemorySize, SM_BIG);
    cudaFuncSetAttribute(s_mma,    cudaFuncAttributeMaxDynamicSharedMemorySize, SM_BIG);
    cudaFuncSetAttribute(proj_mma, cudaFuncAttributeMaxDynamicSharedMemorySize, SM_BIG);
    cudaFuncSetAttribute(o_mma,    cudaFuncAttributeMaxDynamicSharedMemorySize, SM_O);

    dim3 blk(256);

    // single fused split over x, w_qkv, w_proj
    split_all_kernel<<<(N4_TOTAL + 255) / 256, blk>>>(
        (const float4*)x, (const float4*)w_qkv, (const float4*)w_proj);

    qkv_mma<<<dim3(QKV_N / 128, M_TOK / 128), blk, SM_BIG>>>();

    vt_kernel<<<dim3(SEQ / 32, HEAD_DIM / 32, BH), dim3(32, 8)>>>();

    s_mma<<<dim3(SEQ / 128, SEQ / 128, BH), blk, SM_BIG>>>(attn_ptr);

    softmax_kernel<<<dim3(BH * SEQ), blk>>>(attn_ptr);

    o_mma<<<dim3(SEQ / 128, BH), blk, SM_O>>>();

    proj_mma<<<dim3(DIMC / 128, M_TOK / 128), blk, SM_BIG>>>(b_proj, out_ptr);
}

// round 14
// speedup vs baseline: 1.3538x; 1.0216x over previous
#include <cuda_runtime.h>
#include <cuda_bf16.h>
#include <cstdint>

// ============================================================================
// Attention_84129819394524 — R13 champion (479us) + two bounded shavings:
//   1. V-transpose fused into qkv epilogue (vt_kernel deleted)
//   2. 8B packed stores in the fused split kernel
// All other kernels byte-identical to R13.
// ============================================================================

#define NUM_HEADS 12
#define HEAD_DIM  64
#define DIMC      768
#define BATCH     4
#define SEQ       1024
#define SCALE_F   0.125f

#define M_TOK   (BATCH * SEQ)          // 4096
#define QKV_N   (3 * DIMC)             // 2304
#define BH      (BATCH * NUM_HEADS)    // 48

#define OUT_ELEMS  ((size_t)M_TOK * DIMC)
#define ATTN_ELEMS ((size_t)BH * SEQ * SEQ)

// ---------------- device scratch (allocation-free) ----------------
__device__ __align__(16) __nv_bfloat16 g_xh [M_TOK * DIMC];
__device__ __align__(16) __nv_bfloat16 g_xl [M_TOK * DIMC];
__device__ __align__(16) __nv_bfloat16 g_wqh[QKV_N * DIMC];
__device__ __align__(16) __nv_bfloat16 g_wql[QKV_N * DIMC];
__device__ __align__(16) __nv_bfloat16 g_wph[DIMC * DIMC];
__device__ __align__(16) __nv_bfloat16 g_wpl[DIMC * DIMC];
__device__ __align__(16) __nv_bfloat16 g_qh [BH * SEQ * HEAD_DIM];
__device__ __align__(16) __nv_bfloat16 g_ql [BH * SEQ * HEAD_DIM];
__device__ __align__(16) __nv_bfloat16 g_kh [BH * SEQ * HEAD_DIM];
__device__ __align__(16) __nv_bfloat16 g_kl [BH * SEQ * HEAD_DIM];
__device__ __align__(16) __nv_bfloat16 g_vth[BH * HEAD_DIM * SEQ];   // V^T direct
__device__ __align__(16) __nv_bfloat16 g_vtl[BH * HEAD_DIM * SEQ];
__device__ __align__(16) __nv_bfloat16 g_ph [BH * SEQ * SEQ];
__device__ __align__(16) __nv_bfloat16 g_pl [BH * SEQ * SEQ];
__device__ __align__(16) __nv_bfloat16 g_oh [M_TOK * DIMC];
__device__ __align__(16) __nv_bfloat16 g_ol [M_TOK * DIMC];
__device__ __align__(256) float g_attn[ATTN_ELEMS];
__device__ __align__(256) float g_outs[OUT_ELEMS];

// ---------------- helpers ----------------
__device__ __forceinline__ uint32_t smem_u32(const void* p) {
    return (uint32_t)__cvta_generic_to_shared(p);
}
__device__ __forceinline__ void cpasync16(uint32_t dst, const void* src) {
    asm volatile("cp.async.cg.shared.global [%0], [%1], 16;" :: "r"(dst), "l"(src));
}
__device__ __forceinline__ void ldsm_x4(uint32_t* r, uint32_t addr) {
    asm volatile("ldmatrix.sync.aligned.m8n8.x4.shared.b16 {%0,%1,%2,%3}, [%4];"
                 : "=r"(r[0]), "=r"(r[1]), "=r"(r[2]), "=r"(r[3]) : "r"(addr));
}
__device__ __forceinline__ void mma16816(float* c, const uint32_t* a, const uint32_t* b) {
    asm volatile("mma.sync.aligned.m16n8k16.row.col.f32.bf16.bf16.f32 "
                 "{%0,%1,%2,%3}, {%4,%5,%6,%7}, {%8,%9}, {%0,%1,%2,%3};"
                 : "+f"(c[0]), "+f"(c[1]), "+f"(c[2]), "+f"(c[3])
                 : "r"(a[0]), "r"(a[1]), "r"(a[2]), "r"(a[3]), "r"(b[0]), "r"(b[1]));
}
__device__ __forceinline__ void split2(float v, __nv_bfloat16& h, __nv_bfloat16& l) {
    h = __float2bfloat16_rn(v);
    l = __float2bfloat16_rn(v - __bfloat162float(h));
}
__device__ __forceinline__ uint32_t pack_bf2(__nv_bfloat16 a, __nv_bfloat16 b) {
    __nv_bfloat162 t(a, b);
    return *(uint32_t*)&t;
}

// ============================================================================
// R4 mainloop (exact): block 128 x BN of C = A @ B^T, 256 threads,
// warps 4(m) x 2(n), warp tile 32x64 / 32x32.  k32 2-stage cp.async, SPAD=40.
// ============================================================================
#define SPAD 40

template<int BN>
__device__ __forceinline__ void gemm_tile(
    const __nv_bfloat16* __restrict__ Agh, const __nv_bfloat16* __restrict__ Agl, int lda,
    const __nv_bfloat16* __restrict__ Bgh, const __nv_bfloat16* __restrict__ Bgl, int ldb,
    int K, float (&acc)[2][BN / 16][4])
{
    extern __shared__ char smem_raw[];
    constexpr int NT   = BN / 16;
    constexpr int ASZ  = 128 * SPAD * 2;
    constexpr int BSZ  = BN  * SPAD * 2;
    constexpr int STAGE = 2 * ASZ + 2 * BSZ;

    const int tid  = threadIdx.x;
    const int lane = tid & 31;
    const int warp = tid >> 5;
    const int wm = (warp >> 1) * 32;
    const int wn = (warp & 1) * (BN / 2);

    const int lc = tid & 3;
    const int lr = tid >> 2;

    const uint32_t sbase = smem_u32(smem_raw);

    auto load_stage = [&](int s, int k0) {
        uint32_t base = sbase + s * STAGE;
#pragma unroll
        for (int rr = 0; rr < 2; rr++) {
            int row = lr + rr * 64;
            uint32_t doff = (uint32_t)(row * SPAD + lc * 8) * 2;
            cpasync16(base + doff,       Agh + (size_t)row * lda + k0 + lc * 8);
            cpasync16(base + ASZ + doff, Agl + (size_t)row * lda + k0 + lc * 8);
        }
#pragma unroll
        for (int rr = 0; rr < BN / 64; rr++) {
            int row = lr + rr * 64;
            uint32_t doff = (uint32_t)(row * SPAD + lc * 8) * 2;
            cpasync16(base + 2 * ASZ + doff,       Bgh + (size_t)row * ldb + k0 + lc * 8);
            cpasync16(base + 2 * ASZ + BSZ + doff, Bgl + (size_t)row * ldb + k0 + lc * 8);
        }
    };

    const int a_row = wm + (lane & 15);
    const int a_co  = (lane >> 4) << 3;
    const int g     = lane >> 3;
    const int b_rowbase = wn + (g >> 1) * 8 + (lane & 7);
    const int b_co  = (g & 1) * 8;

    int niter = K >> 5;
    load_stage(0, 0);
    asm volatile("cp.async.commit_group;");

    for (int it = 0; it < niter; it++) {
        int buf = it & 1;
        if (it + 1 < niter) {
            load_stage(buf ^ 1, (it + 1) * 32);
            asm volatile("cp.async.commit_group;");
            asm volatile("cp.async.wait_group 1;");
        } else {
            asm volatile("cp.async.wait_group 0;");
        }
        __syncthreads();

        uint32_t sb = sbase + buf * STAGE;
#pragma unroll
        for (int k16 = 0; k16 < 32; k16 += 16) {
            uint32_t ah[2][4], al[2][4];
#pragma unroll
            for (int mt = 0; mt < 2; mt++) {
                uint32_t addr = sb + (uint32_t)(((a_row + mt * 16) * SPAD + k16 + a_co) * 2);
                ldsm_x4(ah[mt], addr);
                ldsm_x4(al[mt], addr + ASZ);
            }
            uint32_t bhf[NT][2], blf[NT][2];
#pragma unroll
            for (int u = 0; u < NT; u += 2) {
                uint32_t addr = sb + 2 * ASZ +
                    (uint32_t)(((b_rowbase + u * 8) * SPAD + k16 + b_co) * 2);
                uint32_t t[4];
                ldsm_x4(t, addr);
                bhf[u][0] = t[0]; bhf[u][1] = t[1];
                bhf[u + 1][0] = t[2]; bhf[u + 1][1] = t[3];
                ldsm_x4(t, addr + BSZ);
                blf[u][0] = t[0]; blf[u][1] = t[1];
                blf[u + 1][0] = t[2]; blf[u + 1][1] = t[3];
            }
#pragma unroll
            for (int mt = 0; mt < 2; mt++) {
#pragma unroll
                for (int u = 0; u < NT; u++) {
                    mma16816(acc[mt][u], ah[mt], bhf[u]);
                    mma16816(acc[mt][u], ah[mt], blf[u]);
                    mma16816(acc[mt][u], al[mt], bhf[u]);
                }
            }
        }
        __syncthreads();
    }
}

// ============================================================================
// Fused split: one grid handles x, w_qkv, w_proj  (fp32 -> hi/lo bf16),
// 8B packed stores per plane.
// ============================================================================
#define N4_X  (M_TOK * DIMC / 4)     // 786432
#define N4_WQ (QKV_N * DIMC / 4)     // 442368
#define N4_WP (DIMC * DIMC / 4)      // 147456
#define N4_TOTAL (N4_X + N4_WQ + N4_WP)

__global__ __launch_bounds__(256)
void split_all_kernel(const float4* __restrict__ x, const float4* __restrict__ wq,
                      const float4* __restrict__ wp)
{
    int i = blockIdx.x * blockDim.x + threadIdx.x;
    if (i >= N4_TOTAL) return;

    const float4* src;
    __nv_bfloat16 *hi, *lo;
    int j;
    if (i < N4_X) {
        src = x;  hi = g_xh;  lo = g_xl;  j = i;
    } else if (i < N4_X + N4_WQ) {
        src = wq; hi = g_wqh; lo = g_wql; j = i - N4_X;
    } else {
        src = wp; hi = g_wph; lo = g_wpl; j = i - N4_X - N4_WQ;
    }

    float4 v = src[j];
    __nv_bfloat16 h0, h1, h2, h3, l0, l1, l2, l3;
    split2(v.x, h0, l0); split2(v.y, h1, l1);
    split2(v.z, h2, l2); split2(v.w, h3, l3);
    *(uint2*)&hi[4 * j] = make_uint2(pack_bf2(h0, h1), pack_bf2(h2, h3));
    *(uint2*)&lo[4 * j] = make_uint2(pack_bf2(l0, l1), pack_bf2(l2, l3));
}

// ============================================================================
// K1: QKV GEMM [4096 x 2304] (R4 mainloop).  Epilogue: q (scaled) / k ->
// [B,H,S,D] hi/lo; v -> TRANSPOSED [B,H,D,S] hi/lo (vt kernel eliminated).
// ============================================================================
__global__ __launch_bounds__(256)
void qkv_mma()
{
    float acc[2][8][4];
#pragma unroll
    for (int a = 0; a < 2; a++)
#pragma unroll
        for (int b = 0; b < 8; b++)
#pragma unroll
            for (int c = 0; c < 4; c++) acc[a][b][c] = 0.f;

    const int bx = blockIdx.x, by = blockIdx.y;
    gemm_tile<128>(g_xh + (size_t)(by * 128) * DIMC, g_xl + (size_t)(by * 128) * DIMC, DIMC,
                   g_wqh + (size_t)(bx * 128) * DIMC, g_wql + (size_t)(bx * 128) * DIMC, DIMC,
                   DIMC, acc);

    const int lane = threadIdx.x & 31, warp = threadIdx.x >> 5;
    const int wm = (warp >> 1) * 32, wn = (warp & 1) * 64;
    const int r = lane >> 2, cc = (lane & 3) * 2;

    const int which = bx / 6;           // 0:q 1:k 2:v
    const int cbase = bx * 128 - which * DIMC;

    if (which < 2) {
        __nv_bfloat16* dh = which ? g_kh : g_qh;
        __nv_bfloat16* dl = which ? g_kl : g_ql;
        const float scl = which ? 1.f : SCALE_F;
#pragma unroll
        for (int mt = 0; mt < 2; mt++) {
#pragma unroll
            for (int nt = 0; nt < 8; nt++) {
                int c = cbase + wn + nt * 8 + cc;
                int h = c >> 6, d = c & 63;
#pragma unroll
                for (int half = 0; half < 2; half++) {
                    int m = by * 128 + wm + mt * 16 + r + half * 8;
                    int b = m >> 10, qi = m & 1023;
                    size_t idx = (((size_t)(b * NUM_HEADS + h) * SEQ) + qi) * HEAD_DIM + d;
                    float v0 = acc[mt][nt][half * 2]     * scl;
                    float v1 = acc[mt][nt][half * 2 + 1] * scl;
                    __nv_bfloat16 h0, h1, l0, l1;
                    split2(v0, h0, l0); split2(v1, h1, l1);
                    *(__nv_bfloat162*)&dh[idx] = __nv_bfloat162(h0, h1);
                    *(__nv_bfloat162*)&dl[idx] = __nv_bfloat162(l0, l1);
                }
            }
        }
    } else {
        // V: write transposed vt[bh][d][qi].  Lanes sharing d cover 8
        // consecutive qi -> 16B runs per 2B store group (2x write amp max).
#pragma unroll
        for (int mt = 0; mt < 2; mt++) {
#pragma unroll
            for (int nt = 0; nt < 8; nt++) {
                int c = cbase + wn + nt * 8 + cc;
                int h = c >> 6, d = c & 63;
#pragma unroll
                for (int half = 0; half < 2; half++) {
                    int m = by * 128 + wm + mt * 16 + r + half * 8;
                    int b = m >> 10, qi = m & 1023;
                    size_t tb = ((size_t)(b * NUM_HEADS + h) * HEAD_DIM + d) * SEQ + qi;
                    float v0 = acc[mt][nt][half * 2];
                    float v1 = acc[mt][nt][half * 2 + 1];
                    __nv_bfloat16 h0, h1, l0, l1;
                    split2(v0, h0, l0); split2(v1, h1, l1);
                    g_vth[tb]       = h0;  g_vtl[tb]       = l0;
                    g_vth[tb + SEQ] = h1;  g_vtl[tb + SEQ] = l1;
                }
            }
        }
    }
}

// ============================================================================
// K3: S = q @ k^T per (b,h) (R13 exact).
// ============================================================================
__global__ __launch_bounds__(256)
void s_mma(float* attn_out)
{
    float* attn = attn_out ? attn_out : g_attn;
    float acc[2][8][4];
#pragma unroll
    for (int a = 0; a < 2; a++)
#pragma unroll
        for (int b = 0; b < 8; b++)
#pragma unroll
            for (int c = 0; c < 4; c++) acc[a][b][c] = 0.f;

    const int bh = blockIdx.z, bx = blockIdx.x, by = blockIdx.y;
    const size_t hb = (size_t)bh * SEQ * HEAD_DIM;
    gemm_tile<128>(g_qh + hb + (size_t)(by * 128) * HEAD_DIM,
                   g_ql + hb + (size_t)(by * 128) * HEAD_DIM, HEAD_DIM,
                   g_kh + hb + (size_t)(bx * 128) * HEAD_DIM,
                   g_kl + hb + (size_t)(bx * 128) * HEAD_DIM, HEAD_DIM,
                   HEAD_DIM, acc);

    const int lane = threadIdx.x & 31, warp = threadIdx.x >> 5;
    const int wm = (warp >> 1) * 32, wn = (warp & 1) * 64;
    const int r = lane >> 2, cc = (lane & 3) * 2;
    float* C = attn + (size_t)bh * SEQ * SEQ;

#pragma unroll
    for (int mt = 0; mt < 2; mt++) {
#pragma unroll
        for (int nt = 0; nt < 8; nt++) {
            int n = bx * 128 + wn + nt * 8 + cc;
#pragma unroll
            for (int half = 0; half < 2; half++) {
                int m = by * 128 + wm + mt * 16 + r + half * 8;
                *(float2*)&C[(size_t)m * SEQ + n] =
                    make_float2(acc[mt][nt][half * 2], acc[mt][nt][half * 2 + 1]);
            }
        }
    }
}

// ============================================================================
// K4: row softmax in place + emit P hi/lo (R13 exact: __expf, packed 8B)
// ============================================================================
__global__ __launch_bounds__(256)
void softmax_kernel(float* attn_out)
{
    float* attn = attn_out ? attn_out : g_attn;
    float* p = attn + (size_t)blockIdx.x * SEQ;
    const size_t pbase = (size_t)blockIdx.x * SEQ;
    const int tid = threadIdx.x;
    __shared__ float red_max[8];
    __shared__ float red_sum[8];

    float4 v = reinterpret_cast<float4*>(p)[tid];
    float m = fmaxf(fmaxf(v.x, v.y), fmaxf(v.z, v.w));
#pragma unroll
    for (int o = 16; o > 0; o >>= 1) m = fmaxf(m, __shfl_xor_sync(0xFFFFFFFFu, m, o));
    if ((tid & 31) == 0) red_max[tid >> 5] = m;
    __syncthreads();
    if (tid == 0) {
        float t = red_max[0];
#pragma unroll
        for (int i = 1; i < 8; i++) t = fmaxf(t, red_max[i]);
        red_max[0] = t;
    }
    __syncthreads();
    const float rmax = red_max[0];

    v.x = __expf(v.x - rmax); v.y = __expf(v.y - rmax);
    v.z = __expf(v.z - rmax); v.w = __expf(v.w - rmax);
    float s = v.x + v.y + v.z + v.w;
#pragma unroll
    for (int o = 16; o > 0; o >>= 1) s += __shfl_xor_sync(0xFFFFFFFFu, s, o);
    if ((tid & 31) == 0) red_sum[tid >> 5] = s;
    __syncthreads();
    if (tid == 0) {
        float t = 0.f;
#pragma unroll
        for (int i = 0; i < 8; i++) t += red_sum[i];
        red_sum[0] = t;
    }
    __syncthreads();
    const float inv = 1.0f / red_sum[0];
    v.x *= inv; v.y *= inv; v.z *= inv; v.w *= inv;
    reinterpret_cast<float4*>(p)[tid] = v;

    __nv_bfloat16 h0, h1, h2, h3, l0, l1, l2, l3;
    split2(v.x, h0, l0); split2(v.y, h1, l1);
    split2(v.z, h2, l2); split2(v.w, h3, l3);
    size_t idx = pbase + tid * 4;
    *(uint2*)&g_ph[idx] = make_uint2(pack_bf2(h0, h1), pack_bf2(h2, h3));
    *(uint2*)&g_pl[idx] = make_uint2(pack_bf2(l0, l1), pack_bf2(l2, l3));
}

// ============================================================================
// K5: O = P @ vt^T per (b,h) (R13 exact).  128x64, K=1024.
// ============================================================================
__global__ __launch_bounds__(256)
void o_mma()
{
    float acc[2][4][4];
#pragma unroll
    for (int a = 0; a < 2; a++)
#pragma unroll
        for (int b = 0; b < 4; b++)
#pragma unroll
            for (int c = 0; c < 4; c++) acc[a][b][c] = 0.f;

    const int bh = blockIdx.y, bx = blockIdx.x;
    const int b = bh / NUM_HEADS, h = bh - b * NUM_HEADS;
    gemm_tile<64>(g_ph + (size_t)bh * SEQ * SEQ + (size_t)(bx * 128) * SEQ,
                  g_pl + (size_t)bh * SEQ * SEQ + (size_t)(bx * 128) * SEQ, SEQ,
                  g_vth + (size_t)bh * HEAD_DIM * SEQ,
                  g_vtl + (size_t)bh * HEAD_DIM * SEQ, SEQ,
                  SEQ, acc);

    const int lane = threadIdx.x & 31, warp = threadIdx.x >> 5;
    const int wm = (warp >> 1) * 32, wn = (warp & 1) * 32;
    const int r = lane >> 2, cc = (lane & 3) * 2;

#pragma unroll
    for (int mt = 0; mt < 2; mt++) {
#pragma unroll
        for (int nt = 0; nt < 4; nt++) {
            int d = wn + nt * 8 + cc;
#pragma unroll
            for (int half = 0; half < 2; half++) {
                int mseq = bx * 128 + wm + mt * 16 + r + half * 8;
                size_t idx = ((size_t)b * SEQ + mseq) * DIMC + h * HEAD_DIM + d;
                float v0 = acc[mt][nt][half * 2];
                float v1 = acc[mt][nt][half * 2 + 1];
                __nv_bfloat16 h0, h1, l0, l1;
                split2(v0, h0, l0); split2(v1, h1, l1);
                *(__nv_bfloat162*)&g_oh[idx] = __nv_bfloat162(h0, h1);
                *(__nv_bfloat162*)&g_ol[idx] = __nv_bfloat162(l0, l1);
            }
        }
    }
}

// ============================================================================
// K6: out = O @ w_proj^T + bias (R13 exact).
// ============================================================================
__global__ __launch_bounds__(256)
void proj_mma(const float* __restrict__ bias, float* out_ptr)
{
    float* outp = out_ptr ? out_ptr : g_outs;
    float acc[2][8][4];
#pragma unroll
    for (int a = 0; a < 2; a++)
#pragma unroll
        for (int b = 0; b < 8; b++)
#pragma unroll
            for (int c = 0; c < 4; c++) acc[a][b][c] = 0.f;

    const int bx = blockIdx.x, by = blockIdx.y;
    gemm_tile<128>(g_oh + (size_t)(by * 128) * DIMC, g_ol + (size_t)(by * 128) * DIMC, DIMC,
                   g_wph + (size_t)(bx * 128) * DIMC, g_wpl + (size_t)(bx * 128) * DIMC, DIMC,
                   DIMC, acc);

    const int lane = threadIdx.x & 31, warp = threadIdx.x >> 5;
    const int wm = (warp >> 1) * 32, wn = (warp & 1) * 64;
    const int r = lane >> 2, cc = (lane & 3) * 2;

#pragma unroll
    for (int mt = 0; mt < 2; mt++) {
#pragma unroll
        for (int nt = 0; nt < 8; nt++) {
            int n = bx * 128 + wn + nt * 8 + cc;
            float b0 = bias[n], b1 = bias[n + 1];
#pragma unroll
            for (int half = 0; half < 2; half++) {
                int m = by * 128 + wm + mt * 16 + r + half * 8;
                *(float2*)&outp[(size_t)m * DIMC + n] =
                    make_float2(acc[mt][nt][half * 2] + b0, acc[mt][nt][half * 2 + 1] + b1);
            }
        }
    }
}

// ============================================================================
// launch (serial, default stream)
// ============================================================================
extern "C" void kernel_launch(void* const* d_in, const int* in_sizes, int n_in,
                              void* d_out, int out_size)
{
    const float* x      = (const float*)d_in[0];
    const float* w_qkv  = (const float*)d_in[1];
    const float* w_proj = (const float*)d_in[2];
    const float* b_proj = (const float*)d_in[3];
    (void)in_sizes; (void)n_in;

    float* dof = (float*)d_out;
    float* out_ptr  = nullptr;
    float* attn_ptr = nullptr;
    size_t osz = (size_t)out_size;
    if (osz >= OUT_ELEMS + ATTN_ELEMS) { out_ptr = dof; attn_ptr = dof + OUT_ELEMS; }
    else if (osz == ATTN_ELEMS)        { attn_ptr = dof; }
    else                               { out_ptr = dof; }

    const int SM_BIG = 2 * (2 * 128 * SPAD * 2 + 2 * 128 * SPAD * 2);  // 81920
    const int SM_O   = 2 * (2 * 128 * SPAD * 2 + 2 * 64  * SPAD * 2);  // 61440
    cudaFuncSetAttribute(qkv_mma,  cudaFuncAttributeMaxDynamicSharedMemorySize, SM_BIG);
    cudaFuncSetAttribute(s_mma,    cudaFuncAttributeMaxDynamicSharedMemorySize, SM_BIG);
    cudaFuncSetAttribute(proj_mma, cudaFuncAttributeMaxDynamicSharedMemorySize, SM_BIG);
    cudaFuncSetAttribute(o_mma,    cudaFuncAttributeMaxDynamicSharedMemorySize, SM_O);

    dim3 blk(256);

    // single fused split over x, w_qkv, w_proj
    split_all_kernel<<<(N4_TOTAL + 255) / 256, blk>>>(
        (const float4*)x, (const float4*)w_qkv, (const float4*)w_proj);

    // QKV GEMM (v written transposed; vt kernel eliminated)
    qkv_mma<<<dim3(QKV_N / 128, M_TOK / 128), blk, SM_BIG>>>();

    s_mma<<<dim3(SEQ / 128, SEQ / 128, BH), blk, SM_BIG>>>(attn_ptr);

    softmax_kernel<<<dim3(BH * SEQ), blk>>>(attn_ptr);

    o_mma<<<dim3(SEQ / 128, BH), blk, SM_O>>>();

    proj_mma<<<dim3(DIMC / 128, M_TOK / 128), blk, SM_BIG>>>(b_proj, out_ptr);
}

// round 15
// speedup vs baseline: 1.5821x; 1.1686x over previous
#include <cuda_runtime.h>
#include <cuda_bf16.h>
#include <cuda_fp16.h>
#include <cstdint>

// ============================================================================
// Attention_84129819394524 — R14 champion (469us) + precision-budget rebalance:
//   qkv: bf16 3-term (unchanged, err ~1.6e-5) — feeds everything.
//   s / o / proj: fp16 asymmetric 2-MMA  C = A_h*(B_h+B_l); A single fp16
//   plane (err ~2.8e-4/GEMM, chained ~5e-4 < 1e-3 threshold).
//   Cascade: q, P, O single-plane -> softmax P write halves, o P read halves.
// ============================================================================

#define NUM_HEADS 12
#define HEAD_DIM  64
#define DIMC      768
#define BATCH     4
#define SEQ       1024
#define SCALE_F   0.125f

#define M_TOK   (BATCH * SEQ)          // 4096
#define QKV_N   (3 * DIMC)             // 2304
#define BH      (BATCH * NUM_HEADS)    // 48

#define OUT_ELEMS  ((size_t)M_TOK * DIMC)
#define ATTN_ELEMS ((size_t)BH * SEQ * SEQ)

// ---------------- device scratch (allocation-free) ----------------
// bf16 (qkv GEMM inputs, 3-term)
__device__ __align__(16) __nv_bfloat16 g_xh [M_TOK * DIMC];
__device__ __align__(16) __nv_bfloat16 g_xl [M_TOK * DIMC];
__device__ __align__(16) __nv_bfloat16 g_wqh[QKV_N * DIMC];
__device__ __align__(16) __nv_bfloat16 g_wql[QKV_N * DIMC];
// fp16 (attention + projection path, 2-term)
__device__ __align__(16) __half g_qf  [BH * SEQ * HEAD_DIM];          // q single
__device__ __align__(16) __half g_kfh [BH * SEQ * HEAD_DIM];
__device__ __align__(16) __half g_kfl [BH * SEQ * HEAD_DIM];
__device__ __align__(16) __half g_vfth[BH * HEAD_DIM * SEQ];          // V^T hi
__device__ __align__(16) __half g_vftl[BH * HEAD_DIM * SEQ];          // V^T lo
__device__ __align__(16) __half g_pf  [BH * SEQ * SEQ];               // P single
__device__ __align__(16) __half g_of  [M_TOK * DIMC];                 // O single
__device__ __align__(16) __half g_wpfh[DIMC * DIMC];
__device__ __align__(16) __half g_wpfl[DIMC * DIMC];
__device__ __align__(256) float g_attn[ATTN_ELEMS];
__device__ __align__(256) float g_outs[OUT_ELEMS];

// ---------------- helpers ----------------
__device__ __forceinline__ uint32_t smem_u32(const void* p) {
    return (uint32_t)__cvta_generic_to_shared(p);
}
__device__ __forceinline__ void cpasync16(uint32_t dst, const void* src) {
    asm volatile("cp.async.cg.shared.global [%0], [%1], 16;" :: "r"(dst), "l"(src));
}
__device__ __forceinline__ void ldsm_x4(uint32_t* r, uint32_t addr) {
    asm volatile("ldmatrix.sync.aligned.m8n8.x4.shared.b16 {%0,%1,%2,%3}, [%4];"
                 : "=r"(r[0]), "=r"(r[1]), "=r"(r[2]), "=r"(r[3]) : "r"(addr));
}
__device__ __forceinline__ void mma_bf16(float* c, const uint32_t* a, const uint32_t* b) {
    asm volatile("mma.sync.aligned.m16n8k16.row.col.f32.bf16.bf16.f32 "
                 "{%0,%1,%2,%3}, {%4,%5,%6,%7}, {%8,%9}, {%0,%1,%2,%3};"
                 : "+f"(c[0]), "+f"(c[1]), "+f"(c[2]), "+f"(c[3])
                 : "r"(a[0]), "r"(a[1]), "r"(a[2]), "r"(a[3]), "r"(b[0]), "r"(b[1]));
}
__device__ __forceinline__ void mma_f16(float* c, const uint32_t* a, const uint32_t* b) {
    asm volatile("mma.sync.aligned.m16n8k16.row.col.f32.f16.f16.f32 "
                 "{%0,%1,%2,%3}, {%4,%5,%6,%7}, {%8,%9}, {%0,%1,%2,%3};"
                 : "+f"(c[0]), "+f"(c[1]), "+f"(c[2]), "+f"(c[3])
                 : "r"(a[0]), "r"(a[1]), "r"(a[2]), "r"(a[3]), "r"(b[0]), "r"(b[1]));
}
__device__ __forceinline__ void split2(float v, __nv_bfloat16& h, __nv_bfloat16& l) {
    h = __float2bfloat16_rn(v);
    l = __float2bfloat16_rn(v - __bfloat162float(h));
}
__device__ __forceinline__ void split2h(float v, __half& h, __half& l) {
    h = __float2half_rn(v);
    l = __float2half_rn(v - __half2float(h));
}
__device__ __forceinline__ uint32_t pack_bf2(__nv_bfloat16 a, __nv_bfloat16 b) {
    __nv_bfloat162 t(a, b);
    return *(uint32_t*)&t;
}
__device__ __forceinline__ uint32_t pack_h2(__half a, __half b) {
    __half2 t(a, b);
    return *(uint32_t*)&t;
}

#define SPAD 40

// ============================================================================
// bf16 3-term mainloop (R4 exact) — used by qkv only.
// ============================================================================
template<int BN>
__device__ __forceinline__ void gemm_tile(
    const __nv_bfloat16* __restrict__ Agh, const __nv_bfloat16* __restrict__ Agl, int lda,
    const __nv_bfloat16* __restrict__ Bgh, const __nv_bfloat16* __restrict__ Bgl, int ldb,
    int K, float (&acc)[2][BN / 16][4])
{
    extern __shared__ char smem_raw[];
    constexpr int NT   = BN / 16;
    constexpr int ASZ  = 128 * SPAD * 2;
    constexpr int BSZ  = BN  * SPAD * 2;
    constexpr int STAGE = 2 * ASZ + 2 * BSZ;

    const int tid  = threadIdx.x;
    const int lane = tid & 31;
    const int warp = tid >> 5;
    const int wm = (warp >> 1) * 32;
    const int wn = (warp & 1) * (BN / 2);
    const int lc = tid & 3;
    const int lr = tid >> 2;
    const uint32_t sbase = smem_u32(smem_raw);

    auto load_stage = [&](int s, int k0) {
        uint32_t base = sbase + s * STAGE;
#pragma unroll
        for (int rr = 0; rr < 2; rr++) {
            int row = lr + rr * 64;
            uint32_t doff = (uint32_t)(row * SPAD + lc * 8) * 2;
            cpasync16(base + doff,       Agh + (size_t)row * lda + k0 + lc * 8);
            cpasync16(base + ASZ + doff, Agl + (size_t)row * lda + k0 + lc * 8);
        }
#pragma unroll
        for (int rr = 0; rr < BN / 64; rr++) {
            int row = lr + rr * 64;
            uint32_t doff = (uint32_t)(row * SPAD + lc * 8) * 2;
            cpasync16(base + 2 * ASZ + doff,       Bgh + (size_t)row * ldb + k0 + lc * 8);
            cpasync16(base + 2 * ASZ + BSZ + doff, Bgl + (size_t)row * ldb + k0 + lc * 8);
        }
    };

    const int a_row = wm + (lane & 15);
    const int a_co  = (lane >> 4) << 3;
    const int g     = lane >> 3;
    const int b_rowbase = wn + (g >> 1) * 8 + (lane & 7);
    const int b_co  = (g & 1) * 8;

    int niter = K >> 5;
    load_stage(0, 0);
    asm volatile("cp.async.commit_group;");

    for (int it = 0; it < niter; it++) {
        int buf = it & 1;
        if (it + 1 < niter) {
            load_stage(buf ^ 1, (it + 1) * 32);
            asm volatile("cp.async.commit_group;");
            asm volatile("cp.async.wait_group 1;");
        } else {
            asm volatile("cp.async.wait_group 0;");
        }
        __syncthreads();

        uint32_t sb = sbase + buf * STAGE;
#pragma unroll
        for (int k16 = 0; k16 < 32; k16 += 16) {
            uint32_t ah[2][4], al[2][4];
#pragma unroll
            for (int mt = 0; mt < 2; mt++) {
                uint32_t addr = sb + (uint32_t)(((a_row + mt * 16) * SPAD + k16 + a_co) * 2);
                ldsm_x4(ah[mt], addr);
                ldsm_x4(al[mt], addr + ASZ);
            }
            uint32_t bhf[NT][2], blf[NT][2];
#pragma unroll
            for (int u = 0; u < NT; u += 2) {
                uint32_t addr = sb + 2 * ASZ +
                    (uint32_t)(((b_rowbase + u * 8) * SPAD + k16 + b_co) * 2);
                uint32_t t[4];
                ldsm_x4(t, addr);
                bhf[u][0] = t[0]; bhf[u][1] = t[1];
                bhf[u + 1][0] = t[2]; bhf[u + 1][1] = t[3];
                ldsm_x4(t, addr + BSZ);
                blf[u][0] = t[0]; blf[u][1] = t[1];
                blf[u + 1][0] = t[2]; blf[u + 1][1] = t[3];
            }
#pragma unroll
            for (int mt = 0; mt < 2; mt++) {
#pragma unroll
                for (int u = 0; u < NT; u++) {
                    mma_bf16(acc[mt][u], ah[mt], bhf[u]);
                    mma_bf16(acc[mt][u], ah[mt], blf[u]);
                    mma_bf16(acc[mt][u], al[mt], bhf[u]);
                }
            }
        }
        __syncthreads();
    }
}

// ============================================================================
// fp16 2-term mainloop: C = A_h*(B_h + B_l).  A single plane, B hi/lo.
// Same tiling/pipeline as above; 2 MMAs per (mt,u), 3 smem planes.
// ============================================================================
template<int BN>
__device__ __forceinline__ void gemm_tile_2t(
    const __half* __restrict__ Ag, int lda,
    const __half* __restrict__ Bgh, const __half* __restrict__ Bgl, int ldb,
    int K, float (&acc)[2][BN / 16][4])
{
    extern __shared__ char smem_raw[];
    constexpr int NT   = BN / 16;
    constexpr int ASZ  = 128 * SPAD * 2;
    constexpr int BSZ  = BN  * SPAD * 2;
    constexpr int STAGE = ASZ + 2 * BSZ;

    const int tid  = threadIdx.x;
    const int lane = tid & 31;
    const int warp = tid >> 5;
    const int wm = (warp >> 1) * 32;
    const int wn = (warp & 1) * (BN / 2);
    const int lc = tid & 3;
    const int lr = tid >> 2;
    const uint32_t sbase = smem_u32(smem_raw);

    auto load_stage = [&](int s, int k0) {
        uint32_t base = sbase + s * STAGE;
#pragma unroll
        for (int rr = 0; rr < 2; rr++) {
            int row = lr + rr * 64;
            uint32_t doff = (uint32_t)(row * SPAD + lc * 8) * 2;
            cpasync16(base + doff, Ag + (size_t)row * lda + k0 + lc * 8);
        }
#pragma unroll
        for (int rr = 0; rr < BN / 64; rr++) {
            int row = lr + rr * 64;
            uint32_t doff = (uint32_t)(row * SPAD + lc * 8) * 2;
            cpasync16(base + ASZ + doff,       Bgh + (size_t)row * ldb + k0 + lc * 8);
            cpasync16(base + ASZ + BSZ + doff, Bgl + (size_t)row * ldb + k0 + lc * 8);
        }
    };

    const int a_row = wm + (lane & 15);
    const int a_co  = (lane >> 4) << 3;
    const int g     = lane >> 3;
    const int b_rowbase = wn + (g >> 1) * 8 + (lane & 7);
    const int b_co  = (g & 1) * 8;

    int niter = K >> 5;
    load_stage(0, 0);
    asm volatile("cp.async.commit_group;");

    for (int it = 0; it < niter; it++) {
        int buf = it & 1;
        if (it + 1 < niter) {
            load_stage(buf ^ 1, (it + 1) * 32);
            asm volatile("cp.async.commit_group;");
            asm volatile("cp.async.wait_group 1;");
        } else {
            asm volatile("cp.async.wait_group 0;");
        }
        __syncthreads();

        uint32_t sb = sbase + buf * STAGE;
#pragma unroll
        for (int k16 = 0; k16 < 32; k16 += 16) {
            uint32_t ah[2][4];
#pragma unroll
            for (int mt = 0; mt < 2; mt++) {
                uint32_t addr = sb + (uint32_t)(((a_row + mt * 16) * SPAD + k16 + a_co) * 2);
                ldsm_x4(ah[mt], addr);
            }
            uint32_t bhf[NT][2], blf[NT][2];
#pragma unroll
            for (int u = 0; u < NT; u += 2) {
                uint32_t addr = sb + ASZ +
                    (uint32_t)(((b_rowbase + u * 8) * SPAD + k16 + b_co) * 2);
                uint32_t t[4];
                ldsm_x4(t, addr);
                bhf[u][0] = t[0]; bhf[u][1] = t[1];
                bhf[u + 1][0] = t[2]; bhf[u + 1][1] = t[3];
                ldsm_x4(t, addr + BSZ);
                blf[u][0] = t[0]; blf[u][1] = t[1];
                blf[u + 1][0] = t[2]; blf[u + 1][1] = t[3];
            }
#pragma unroll
            for (int mt = 0; mt < 2; mt++) {
#pragma unroll
                for (int u = 0; u < NT; u++) {
                    mma_f16(acc[mt][u], ah[mt], bhf[u]);
                    mma_f16(acc[mt][u], ah[mt], blf[u]);
                }
            }
        }
        __syncthreads();
    }
}

// ============================================================================
// Fused split: x, w_qkv -> bf16 hi/lo;  w_proj -> fp16 hi/lo.
// ============================================================================
#define N4_X  (M_TOK * DIMC / 4)     // 786432
#define N4_WQ (QKV_N * DIMC / 4)     // 442368
#define N4_WP (DIMC * DIMC / 4)      // 147456
#define N4_TOTAL (N4_X + N4_WQ + N4_WP)

__global__ __launch_bounds__(256)
void split_all_kernel(const float4* __restrict__ x, const float4* __restrict__ wq,
                      const float4* __restrict__ wp)
{
    int i = blockIdx.x * blockDim.x + threadIdx.x;
    if (i >= N4_TOTAL) return;

    if (i < N4_X + N4_WQ) {
        const float4* src;
        __nv_bfloat16 *hi, *lo;
        int j;
        if (i < N4_X) { src = x;  hi = g_xh;  lo = g_xl;  j = i; }
        else          { src = wq; hi = g_wqh; lo = g_wql; j = i - N4_X; }
        float4 v = src[j];
        __nv_bfloat16 h0, h1, h2, h3, l0, l1, l2, l3;
        split2(v.x, h0, l0); split2(v.y, h1, l1);
        split2(v.z, h2, l2); split2(v.w, h3, l3);
        *(uint2*)&hi[4 * j] = make_uint2(pack_bf2(h0, h1), pack_bf2(h2, h3));
        *(uint2*)&lo[4 * j] = make_uint2(pack_bf2(l0, l1), pack_bf2(l2, l3));
    } else {
        int j = i - N4_X - N4_WQ;
        float4 v = wp[j];
        __half h0, h1, h2, h3, l0, l1, l2, l3;
        split2h(v.x, h0, l0); split2h(v.y, h1, l1);
        split2h(v.z, h2, l2); split2h(v.w, h3, l3);
        *(uint2*)&g_wpfh[4 * j] = make_uint2(pack_h2(h0, h1), pack_h2(h2, h3));
        *(uint2*)&g_wpfl[4 * j] = make_uint2(pack_h2(l0, l1), pack_h2(l2, l3));
    }
}

// ============================================================================
// K1: QKV GEMM (bf16 3-term, R4 mainloop).  Epilogue:
//   q -> single fp16 plane (scaled); k -> fp16 hi/lo; v -> transposed fp16 hi/lo.
// ============================================================================
__global__ __launch_bounds__(256)
void qkv_mma()
{
    float acc[2][8][4];
#pragma unroll
    for (int a = 0; a < 2; a++)
#pragma unroll
        for (int b = 0; b < 8; b++)
#pragma unroll
            for (int c = 0; c < 4; c++) acc[a][b][c] = 0.f;

    const int bx = blockIdx.x, by = blockIdx.y;
    gemm_tile<128>(g_xh + (size_t)(by * 128) * DIMC, g_xl + (size_t)(by * 128) * DIMC, DIMC,
                   g_wqh + (size_t)(bx * 128) * DIMC, g_wql + (size_t)(bx * 128) * DIMC, DIMC,
                   DIMC, acc);

    const int lane = threadIdx.x & 31, warp = threadIdx.x >> 5;
    const int wm = (warp >> 1) * 32, wn = (warp & 1) * 64;
    const int r = lane >> 2, cc = (lane & 3) * 2;

    const int which = bx / 6;           // 0:q 1:k 2:v
    const int cbase = bx * 128 - which * DIMC;

    if (which == 0) {
        // q: single fp16 plane, pre-scaled
#pragma unroll
        for (int mt = 0; mt < 2; mt++) {
#pragma unroll
            for (int nt = 0; nt < 8; nt++) {
                int c = cbase + wn + nt * 8 + cc;
                int h = c >> 6, d = c & 63;
#pragma unroll
                for (int half = 0; half < 2; half++) {
                    int m = by * 128 + wm + mt * 16 + r + half * 8;
                    int b = m >> 10, qi = m & 1023;
                    size_t idx = (((size_t)(b * NUM_HEADS + h) * SEQ) + qi) * HEAD_DIM + d;
                    __half q0 = __float2half_rn(acc[mt][nt][half * 2]     * SCALE_F);
                    __half q1 = __float2half_rn(acc[mt][nt][half * 2 + 1] * SCALE_F);
                    *(__half2*)&g_qf[idx] = __half2(q0, q1);
                }
            }
        }
    } else if (which == 1) {
        // k: fp16 hi/lo
#pragma unroll
        for (int mt = 0; mt < 2; mt++) {
#pragma unroll
            for (int nt = 0; nt < 8; nt++) {
                int c = cbase + wn + nt * 8 + cc;
                int h = c >> 6, d = c & 63;
#pragma unroll
                for (int half = 0; half < 2; half++) {
                    int m = by * 128 + wm + mt * 16 + r + half * 8;
                    int b = m >> 10, qi = m & 1023;
                    size_t idx = (((size_t)(b * NUM_HEADS + h) * SEQ) + qi) * HEAD_DIM + d;
                    __half h0, h1, l0, l1;
                    split2h(acc[mt][nt][half * 2],     h0, l0);
                    split2h(acc[mt][nt][half * 2 + 1], h1, l1);
                    *(__half2*)&g_kfh[idx] = __half2(h0, h1);
                    *(__half2*)&g_kfl[idx] = __half2(l0, l1);
                }
            }
        }
    } else {
        // v: transposed fp16 hi/lo  vt[bh][d][qi]
#pragma unroll
        for (int mt = 0; mt < 2; mt++) {
#pragma unroll
            for (int nt = 0; nt < 8; nt++) {
                int c = cbase + wn + nt * 8 + cc;
                int h = c >> 6, d = c & 63;
#pragma unroll
                for (int half = 0; half < 2; half++) {
                    int m = by * 128 + wm + mt * 16 + r + half * 8;
                    int b = m >> 10, qi = m & 1023;
                    size_t tb = ((size_t)(b * NUM_HEADS + h) * HEAD_DIM + d) * SEQ + qi;
                    __half h0, h1, l0, l1;
                    split2h(acc[mt][nt][half * 2],     h0, l0);
                    split2h(acc[mt][nt][half * 2 + 1], h1, l1);
                    g_vfth[tb]       = h0;  g_vftl[tb]       = l0;
                    g_vfth[tb + SEQ] = h1;  g_vftl[tb + SEQ] = l1;
                }
            }
        }
    }
}

// ============================================================================
// K3: S = q @ k^T per (b,h).  fp16 2-term: q single, k hi/lo.
// ============================================================================
__global__ __launch_bounds__(256)
void s_mma(float* attn_out)
{
    float* attn = attn_out ? attn_out : g_attn;
    float acc[2][8][4];
#pragma unroll
    for (int a = 0; a < 2; a++)
#pragma unroll
        for (int b = 0; b < 8; b++)
#pragma unroll
            for (int c = 0; c < 4; c++) acc[a][b][c] = 0.f;

    const int bh = blockIdx.z, bx = blockIdx.x, by = blockIdx.y;
    const size_t hb = (size_t)bh * SEQ * HEAD_DIM;
    gemm_tile_2t<128>(g_qf + hb + (size_t)(by * 128) * HEAD_DIM, HEAD_DIM,
                      g_kfh + hb + (size_t)(bx * 128) * HEAD_DIM,
                      g_kfl + hb + (size_t)(bx * 128) * HEAD_DIM, HEAD_DIM,
                      HEAD_DIM, acc);

    const int lane = threadIdx.x & 31, warp = threadIdx.x >> 5;
    const int wm = (warp >> 1) * 32, wn = (warp & 1) * 64;
    const int r = lane >> 2, cc = (lane & 3) * 2;
    float* C = attn + (size_t)bh * SEQ * SEQ;

#pragma unroll
    for (int mt = 0; mt < 2; mt++) {
#pragma unroll
        for (int nt = 0; nt < 8; nt++) {
            int n = bx * 128 + wn + nt * 8 + cc;
#pragma unroll
            for (int half = 0; half < 2; half++) {
                int m = by * 128 + wm + mt * 16 + r + half * 8;
                *(float2*)&C[(size_t)m * SEQ + n] =
                    make_float2(acc[mt][nt][half * 2], acc[mt][nt][half * 2 + 1]);
            }
        }
    }
}

// ============================================================================
// K4: row softmax in place + emit P single fp16 plane.
// ============================================================================
__global__ __launch_bounds__(256)
void softmax_kernel(float* attn_out)
{
    float* attn = attn_out ? attn_out : g_attn;
    float* p = attn + (size_t)blockIdx.x * SEQ;
    const size_t pbase = (size_t)blockIdx.x * SEQ;
    const int tid = threadIdx.x;
    __shared__ float red_max[8];
    __shared__ float red_sum[8];

    float4 v = reinterpret_cast<float4*>(p)[tid];
    float m = fmaxf(fmaxf(v.x, v.y), fmaxf(v.z, v.w));
#pragma unroll
    for (int o = 16; o > 0; o >>= 1) m = fmaxf(m, __shfl_xor_sync(0xFFFFFFFFu, m, o));
    if ((tid & 31) == 0) red_max[tid >> 5] = m;
    __syncthreads();
    if (tid == 0) {
        float t = red_max[0];
#pragma unroll
        for (int i = 1; i < 8; i++) t = fmaxf(t, red_max[i]);
        red_max[0] = t;
    }
    __syncthreads();
    const float rmax = red_max[0];

    v.x = __expf(v.x - rmax); v.y = __expf(v.y - rmax);
    v.z = __expf(v.z - rmax); v.w = __expf(v.w - rmax);
    float s = v.x + v.y + v.z + v.w;
#pragma unroll
    for (int o = 16; o > 0; o >>= 1) s += __shfl_xor_sync(0xFFFFFFFFu, s, o);
    if ((tid & 31) == 0) red_sum[tid >> 5] = s;
    __syncthreads();
    if (tid == 0) {
        float t = 0.f;
#pragma unroll
        for (int i = 0; i < 8; i++) t += red_sum[i];
        red_sum[0] = t;
    }
    __syncthreads();
    const float inv = 1.0f / red_sum[0];
    v.x *= inv; v.y *= inv; v.z *= inv; v.w *= inv;
    reinterpret_cast<float4*>(p)[tid] = v;

    size_t idx = pbase + tid * 4;
    *(uint2*)&g_pf[idx] = make_uint2(
        pack_h2(__float2half_rn(v.x), __float2half_rn(v.y)),
        pack_h2(__float2half_rn(v.z), __float2half_rn(v.w)));
}

// ============================================================================
// K5: O = P @ vt^T per (b,h).  fp16 2-term: P single, vt hi/lo.  128x64 K=1024.
// Epilogue: O single fp16 plane in [B,S,C].
// ============================================================================
__global__ __launch_bounds__(256)
void o_mma()
{
    float acc[2][4][4];
#pragma unroll
    for (int a = 0; a < 2; a++)
#pragma unroll
        for (int b = 0; b < 4; b++)
#pragma unroll
            for (int c = 0; c < 4; c++) acc[a][b][c] = 0.f;

    const int bh = blockIdx.y, bx = blockIdx.x;
    const int b = bh / NUM_HEADS, h = bh - b * NUM_HEADS;
    gemm_tile_2t<64>(g_pf + (size_t)bh * SEQ * SEQ + (size_t)(bx * 128) * SEQ, SEQ,
                     g_vfth + (size_t)bh * HEAD_DIM * SEQ,
                     g_vftl + (size_t)bh * HEAD_DIM * SEQ, SEQ,
                     SEQ, acc);

    const int lane = threadIdx.x & 31, warp = threadIdx.x >> 5;
    const int wm = (warp >> 1) * 32, wn = (warp & 1) * 32;
    const int r = lane >> 2, cc = (lane & 3) * 2;

#pragma unroll
    for (int mt = 0; mt < 2; mt++) {
#pragma unroll
        for (int nt = 0; nt < 4; nt++) {
            int d = wn + nt * 8 + cc;
#pragma unroll
            for (int half = 0; half < 2; half++) {
                int mseq = bx * 128 + wm + mt * 16 + r + half * 8;
                size_t idx = ((size_t)b * SEQ + mseq) * DIMC + h * HEAD_DIM + d;
                *(__half2*)&g_of[idx] = __half2(
                    __float2half_rn(acc[mt][nt][half * 2]),
                    __float2half_rn(acc[mt][nt][half * 2 + 1]));
            }
        }
    }
}

// ============================================================================
// K6: out = O @ w_proj^T + bias.  fp16 2-term: O single, wp hi/lo.  fp32 out.
// ============================================================================
__global__ __launch_bounds__(256)
void proj_mma(const float* __restrict__ bias, float* out_ptr)
{
    float* outp = out_ptr ? out_ptr : g_outs;
    float acc[2][8][4];
#pragma unroll
    for (int a = 0; a < 2; a++)
#pragma unroll
        for (int b = 0; b < 8; b++)
#pragma unroll
            for (int c = 0; c < 4; c++) acc[a][b][c] = 0.f;

    const int bx = blockIdx.x, by = blockIdx.y;
    gemm_tile_2t<128>(g_of + (size_t)(by * 128) * DIMC, DIMC,
                      g_wpfh + (size_t)(bx * 128) * DIMC,
                      g_wpfl + (size_t)(bx * 128) * DIMC, DIMC,
                      DIMC, acc);

    const int lane = threadIdx.x & 31, warp = threadIdx.x >> 5;
    const int wm = (warp >> 1) * 32, wn = (warp & 1) * 64;
    const int r = lane >> 2, cc = (lane & 3) * 2;

#pragma unroll
    for (int mt = 0; mt < 2; mt++) {
#pragma unroll
        for (int nt = 0; nt < 8; nt++) {
            int n = bx * 128 + wn + nt * 8 + cc;
            float b0 = bias[n], b1 = bias[n + 1];
#pragma unroll
            for (int half = 0; half < 2; half++) {
                int m = by * 128 + wm + mt * 16 + r + half * 8;
                *(float2*)&outp[(size_t)m * DIMC + n] =
                    make_float2(acc[mt][nt][half * 2] + b0, acc[mt][nt][half * 2 + 1] + b1);
            }
        }
    }
}

// ============================================================================
// launch (serial, default stream)
// ============================================================================
extern "C" void kernel_launch(void* const* d_in, const int* in_sizes, int n_in,
                              void* d_out, int out_size)
{
    const float* x      = (const float*)d_in[0];
    const float* w_qkv  = (const float*)d_in[1];
    const float* w_proj = (const float*)d_in[2];
    const float* b_proj = (const float*)d_in[3];
    (void)in_sizes; (void)n_in;

    float* dof = (float*)d_out;
    float* out_ptr  = nullptr;
    float* attn_ptr = nullptr;
    size_t osz = (size_t)out_size;
    if (osz >= OUT_ELEMS + ATTN_ELEMS) { out_ptr = dof; attn_ptr = dof + OUT_ELEMS; }
    else if (osz == ATTN_ELEMS)        { attn_ptr = dof; }
    else                               { out_ptr = dof; }

    const int SM_QKV = 2 * (2 * 128 * SPAD * 2 + 2 * 128 * SPAD * 2);  // 81920
    const int SM_2T  = 2 * (128 * SPAD * 2 + 2 * 128 * SPAD * 2);      // 61440
    const int SM_O2  = 2 * (128 * SPAD * 2 + 2 * 64 * SPAD * 2);       // 40960
    cudaFuncSetAttribute(qkv_mma,  cudaFuncAttributeMaxDynamicSharedMemorySize, SM_QKV);
    cudaFuncSetAttribute(s_mma,    cudaFuncAttributeMaxDynamicSharedMemorySize, SM_2T);
    cudaFuncSetAttribute(proj_mma, cudaFuncAttributeMaxDynamicSharedMemorySize, SM_2T);
    cudaFuncSetAttribute(o_mma,    cudaFuncAttributeMaxDynamicSharedMemorySize, SM_O2);

    dim3 blk(256);

    split_all_kernel<<<(N4_TOTAL + 255) / 256, blk>>>(
        (const float4*)x, (const float4*)w_qkv, (const float4*)w_proj);

    qkv_mma<<<dim3(QKV_N / 128, M_TOK / 128), blk, SM_QKV>>>();

    s_mma<<<dim3(SEQ / 128, SEQ / 128, BH), blk, SM_2T>>>(attn_ptr);

    softmax_kernel<<<dim3(BH * SEQ), blk>>>(attn_ptr);

    o_mma<<<dim3(SEQ / 128, BH), blk, SM_O2>>>();

    proj_mma<<<dim3(DIMC / 128, M_TOK / 128), blk, SM_2T>>>(b_proj, out_ptr);
}

// round 17
// speedup vs baseline: 1.7325x; 1.0951x over previous
#include <cuda_runtime.h>
#include <cuda_fp16.h>
#include <cstdint>

// ============================================================================
// Attention_84129819394524 — R15 champion (401us) + qkv moved to fp16
// asymmetric 2-term (x single plane, w hi/lo).  Whole pipeline now fp16:
//   C = A_h * (B_h + B_l), fp32 accum.  Calibrated error ~2e-4/stage (RSS).
// (Resubmission of R16 — container infra failure, kernel never executed.)
// ============================================================================

#define NUM_HEADS 12
#define HEAD_DIM  64
#define DIMC      768
#define BATCH     4
#define SEQ       1024
#define SCALE_F   0.125f

#define M_TOK   (BATCH * SEQ)          // 4096
#define QKV_N   (3 * DIMC)             // 2304
#define BH      (BATCH * NUM_HEADS)    // 48

#define OUT_ELEMS  ((size_t)M_TOK * DIMC)
#define ATTN_ELEMS ((size_t)BH * SEQ * SEQ)

// ---------------- device scratch (allocation-free) ----------------
__device__ __align__(16) __half g_xf  [M_TOK * DIMC];                 // x single
__device__ __align__(16) __half g_wqfh[QKV_N * DIMC];
__device__ __align__(16) __half g_wqfl[QKV_N * DIMC];
__device__ __align__(16) __half g_qf  [BH * SEQ * HEAD_DIM];          // q single
__device__ __align__(16) __half g_kfh [BH * SEQ * HEAD_DIM];
__device__ __align__(16) __half g_kfl [BH * SEQ * HEAD_DIM];
__device__ __align__(16) __half g_vfth[BH * HEAD_DIM * SEQ];          // V^T hi
__device__ __align__(16) __half g_vftl[BH * HEAD_DIM * SEQ];          // V^T lo
__device__ __align__(16) __half g_pf  [BH * SEQ * SEQ];               // P single
__device__ __align__(16) __half g_of  [M_TOK * DIMC];                 // O single
__device__ __align__(16) __half g_wpfh[DIMC * DIMC];
__device__ __align__(16) __half g_wpfl[DIMC * DIMC];
__device__ __align__(256) float g_attn[ATTN_ELEMS];
__device__ __align__(256) float g_outs[OUT_ELEMS];

// ---------------- helpers ----------------
__device__ __forceinline__ uint32_t smem_u32(const void* p) {
    return (uint32_t)__cvta_generic_to_shared(p);
}
__device__ __forceinline__ void cpasync16(uint32_t dst, const void* src) {
    asm volatile("cp.async.cg.shared.global [%0], [%1], 16;" :: "r"(dst), "l"(src));
}
__device__ __forceinline__ void ldsm_x4(uint32_t* r, uint32_t addr) {
    asm volatile("ldmatrix.sync.aligned.m8n8.x4.shared.b16 {%0,%1,%2,%3}, [%4];"
                 : "=r"(r[0]), "=r"(r[1]), "=r"(r[2]), "=r"(r[3]) : "r"(addr));
}
__device__ __forceinline__ void mma_f16(float* c, const uint32_t* a, const uint32_t* b) {
    asm volatile("mma.sync.aligned.m16n8k16.row.col.f32.f16.f16.f32 "
                 "{%0,%1,%2,%3}, {%4,%5,%6,%7}, {%8,%9}, {%0,%1,%2,%3};"
                 : "+f"(c[0]), "+f"(c[1]), "+f"(c[2]), "+f"(c[3])
                 : "r"(a[0]), "r"(a[1]), "r"(a[2]), "r"(a[3]), "r"(b[0]), "r"(b[1]));
}
__device__ __forceinline__ void split2h(float v, __half& h, __half& l) {
    h = __float2half_rn(v);
    l = __float2half_rn(v - __half2float(h));
}
__device__ __forceinline__ uint32_t pack_h2(__half a, __half b) {
    __half2 t(a, b);
    return *(uint32_t*)&t;
}

#define SPAD 40

// ============================================================================
// fp16 2-term mainloop: C = A_h*(B_h + B_l).  A single plane, B hi/lo.
// block 128 x BN, 256 threads, warps 4(m) x 2(n), k32 2-stage cp.async.
// ============================================================================
template<int BN>
__device__ __forceinline__ void gemm_tile_2t(
    const __half* __restrict__ Ag, int lda,
    const __half* __restrict__ Bgh, const __half* __restrict__ Bgl, int ldb,
    int K, float (&acc)[2][BN / 16][4])
{
    extern __shared__ char smem_raw[];
    constexpr int NT   = BN / 16;
    constexpr int ASZ  = 128 * SPAD * 2;
    constexpr int BSZ  = BN  * SPAD * 2;
    constexpr int STAGE = ASZ + 2 * BSZ;

    const int tid  = threadIdx.x;
    const int lane = tid & 31;
    const int warp = tid >> 5;
    const int wm = (warp >> 1) * 32;
    const int wn = (warp & 1) * (BN / 2);
    const int lc = tid & 3;
    const int lr = tid >> 2;
    const uint32_t sbase = smem_u32(smem_raw);

    auto load_stage = [&](int s, int k0) {
        uint32_t base = sbase + s * STAGE;
#pragma unroll
        for (int rr = 0; rr < 2; rr++) {
            int row = lr + rr * 64;
            uint32_t doff = (uint32_t)(row * SPAD + lc * 8) * 2;
            cpasync16(base + doff, Ag + (size_t)row * lda + k0 + lc * 8);
        }
#pragma unroll
        for (int rr = 0; rr < BN / 64; rr++) {
            int row = lr + rr * 64;
            uint32_t doff = (uint32_t)(row * SPAD + lc * 8) * 2;
            cpasync16(base + ASZ + doff,       Bgh + (size_t)row * ldb + k0 + lc * 8);
            cpasync16(base + ASZ + BSZ + doff, Bgl + (size_t)row * ldb + k0 + lc * 8);
        }
    };

    const int a_row = wm + (lane & 15);
    const int a_co  = (lane >> 4) << 3;
    const int g     = lane >> 3;
    const int b_rowbase = wn + (g >> 1) * 8 + (lane & 7);
    const int b_co  = (g & 1) * 8;

    int niter = K >> 5;
    load_stage(0, 0);
    asm volatile("cp.async.commit_group;");

    for (int it = 0; it < niter; it++) {
        int buf = it & 1;
        if (it + 1 < niter) {
            load_stage(buf ^ 1, (it + 1) * 32);
            asm volatile("cp.async.commit_group;");
            asm volatile("cp.async.wait_group 1;");
        } else {
            asm volatile("cp.async.wait_group 0;");
        }
        __syncthreads();

        uint32_t sb = sbase + buf * STAGE;
#pragma unroll
        for (int k16 = 0; k16 < 32; k16 += 16) {
            uint32_t ah[2][4];
#pragma unroll
            for (int mt = 0; mt < 2; mt++) {
                uint32_t addr = sb + (uint32_t)(((a_row + mt * 16) * SPAD + k16 + a_co) * 2);
                ldsm_x4(ah[mt], addr);
            }
            uint32_t bhf[NT][2], blf[NT][2];
#pragma unroll
            for (int u = 0; u < NT; u += 2) {
                uint32_t addr = sb + ASZ +
                    (uint32_t)(((b_rowbase + u * 8) * SPAD + k16 + b_co) * 2);
                uint32_t t[4];
                ldsm_x4(t, addr);
                bhf[u][0] = t[0]; bhf[u][1] = t[1];
                bhf[u + 1][0] = t[2]; bhf[u + 1][1] = t[3];
                ldsm_x4(t, addr + BSZ);
                blf[u][0] = t[0]; blf[u][1] = t[1];
                blf[u + 1][0] = t[2]; blf[u + 1][1] = t[3];
            }
#pragma unroll
            for (int mt = 0; mt < 2; mt++) {
#pragma unroll
                for (int u = 0; u < NT; u++) {
                    mma_f16(acc[mt][u], ah[mt], bhf[u]);
                    mma_f16(acc[mt][u], ah[mt], blf[u]);
                }
            }
        }
        __syncthreads();
    }
}

// ============================================================================
// Fused split: x -> single fp16; w_qkv, w_proj -> fp16 hi/lo.
// ============================================================================
#define N4_X  (M_TOK * DIMC / 4)     // 786432
#define N4_WQ (QKV_N * DIMC / 4)     // 442368
#define N4_WP (DIMC * DIMC / 4)      // 147456
#define N4_TOTAL (N4_X + N4_WQ + N4_WP)

__global__ __launch_bounds__(256)
void split_all_kernel(const float4* __restrict__ x, const float4* __restrict__ wq,
                      const float4* __restrict__ wp)
{
    int i = blockIdx.x * blockDim.x + threadIdx.x;
    if (i >= N4_TOTAL) return;

    if (i < N4_X) {
        float4 v = x[i];
        *(uint2*)&g_xf[4 * i] = make_uint2(
            pack_h2(__float2half_rn(v.x), __float2half_rn(v.y)),
            pack_h2(__float2half_rn(v.z), __float2half_rn(v.w)));
    } else {
        const float4* src;
        __half *hi, *lo;
        int j;
        if (i < N4_X + N4_WQ) { src = wq; hi = g_wqfh; lo = g_wqfl; j = i - N4_X; }
        else                  { src = wp; hi = g_wpfh; lo = g_wpfl; j = i - N4_X - N4_WQ; }
        float4 v = src[j];
        __half h0, h1, h2, h3, l0, l1, l2, l3;
        split2h(v.x, h0, l0); split2h(v.y, h1, l1);
        split2h(v.z, h2, l2); split2h(v.w, h3, l3);
        *(uint2*)&hi[4 * j] = make_uint2(pack_h2(h0, h1), pack_h2(h2, h3));
        *(uint2*)&lo[4 * j] = make_uint2(pack_h2(l0, l1), pack_h2(l2, l3));
    }
}

// ============================================================================
// K1: QKV GEMM (fp16 2-term: x single, wq hi/lo).  Epilogue:
//   q -> single fp16 (scaled); k -> fp16 hi/lo; v -> transposed fp16 hi/lo.
// ============================================================================
__global__ __launch_bounds__(256)
void qkv_mma()
{
    float acc[2][8][4];
#pragma unroll
    for (int a = 0; a < 2; a++)
#pragma unroll
        for (int b = 0; b < 8; b++)
#pragma unroll
            for (int c = 0; c < 4; c++) acc[a][b][c] = 0.f;

    const int bx = blockIdx.x, by = blockIdx.y;
    gemm_tile_2t<128>(g_xf + (size_t)(by * 128) * DIMC, DIMC,
                      g_wqfh + (size_t)(bx * 128) * DIMC,
                      g_wqfl + (size_t)(bx * 128) * DIMC, DIMC,
                      DIMC, acc);

    const int lane = threadIdx.x & 31, warp = threadIdx.x >> 5;
    const int wm = (warp >> 1) * 32, wn = (warp & 1) * 64;
    const int r = lane >> 2, cc = (lane & 3) * 2;

    const int which = bx / 6;           // 0:q 1:k 2:v
    const int cbase = bx * 128 - which * DIMC;

    if (which == 0) {
#pragma unroll
        for (int mt = 0; mt < 2; mt++) {
#pragma unroll
            for (int nt = 0; nt < 8; nt++) {
                int c = cbase + wn + nt * 8 + cc;
                int h = c >> 6, d = c & 63;
#pragma unroll
                for (int half = 0; half < 2; half++) {
                    int m = by * 128 + wm + mt * 16 + r + half * 8;
                    int b = m >> 10, qi = m & 1023;
                    size_t idx = (((size_t)(b * NUM_HEADS + h) * SEQ) + qi) * HEAD_DIM + d;
                    __half q0 = __float2half_rn(acc[mt][nt][half * 2]     * SCALE_F);
                    __half q1 = __float2half_rn(acc[mt][nt][half * 2 + 1] * SCALE_F);
                    *(__half2*)&g_qf[idx] = __half2(q0, q1);
                }
            }
        }
    } else if (which == 1) {
#pragma unroll
        for (int mt = 0; mt < 2; mt++) {
#pragma unroll
            for (int nt = 0; nt < 8; nt++) {
                int c = cbase + wn + nt * 8 + cc;
                int h = c >> 6, d = c & 63;
#pragma unroll
                for (int half = 0; half < 2; half++) {
                    int m = by * 128 + wm + mt * 16 + r + half * 8;
                    int b = m >> 10, qi = m & 1023;
                    size_t idx = (((size_t)(b * NUM_HEADS + h) * SEQ) + qi) * HEAD_DIM + d;
                    __half h0, h1, l0, l1;
                    split2h(acc[mt][nt][half * 2],     h0, l0);
                    split2h(acc[mt][nt][half * 2 + 1], h1, l1);
                    *(__half2*)&g_kfh[idx] = __half2(h0, h1);
                    *(__half2*)&g_kfl[idx] = __half2(l0, l1);
                }
            }
        }
    } else {
#pragma unroll
        for (int mt = 0; mt < 2; mt++) {
#pragma unroll
            for (int nt = 0; nt < 8; nt++) {
                int c = cbase + wn + nt * 8 + cc;
                int h = c >> 6, d = c & 63;
#pragma unroll
                for (int half = 0; half < 2; half++) {
                    int m = by * 128 + wm + mt * 16 + r + half * 8;
                    int b = m >> 10, qi = m & 1023;
                    size_t tb = ((size_t)(b * NUM_HEADS + h) * HEAD_DIM + d) * SEQ + qi;
                    __half h0, h1, l0, l1;
                    split2h(acc[mt][nt][half * 2],     h0, l0);
                    split2h(acc[mt][nt][half * 2 + 1], h1, l1);
                    g_vfth[tb]       = h0;  g_vftl[tb]       = l0;
                    g_vfth[tb + SEQ] = h1;  g_vftl[tb + SEQ] = l1;
                }
            }
        }
    }
}

// ============================================================================
// K3: S = q @ k^T per (b,h).  fp16 2-term: q single, k hi/lo.
// ============================================================================
__global__ __launch_bounds__(256)
void s_mma(float* attn_out)
{
    float* attn = attn_out ? attn_out : g_attn;
    float acc[2][8][4];
#pragma unroll
    for (int a = 0; a < 2; a++)
#pragma unroll
        for (int b = 0; b < 8; b++)
#pragma unroll
            for (int c = 0; c < 4; c++) acc[a][b][c] = 0.f;

    const int bh = blockIdx.z, bx = blockIdx.x, by = blockIdx.y;
    const size_t hb = (size_t)bh * SEQ * HEAD_DIM;
    gemm_tile_2t<128>(g_qf + hb + (size_t)(by * 128) * HEAD_DIM, HEAD_DIM,
                      g_kfh + hb + (size_t)(bx * 128) * HEAD_DIM,
                      g_kfl + hb + (size_t)(bx * 128) * HEAD_DIM, HEAD_DIM,
                      HEAD_DIM, acc);

    const int lane = threadIdx.x & 31, warp = threadIdx.x >> 5;
    const int wm = (warp >> 1) * 32, wn = (warp & 1) * 64;
    const int r = lane >> 2, cc = (lane & 3) * 2;
    float* C = attn + (size_t)bh * SEQ * SEQ;

#pragma unroll
    for (int mt = 0; mt < 2; mt++) {
#pragma unroll
        for (int nt = 0; nt < 8; nt++) {
            int n = bx * 128 + wn + nt * 8 + cc;
#pragma unroll
            for (int half = 0; half < 2; half++) {
                int m = by * 128 + wm + mt * 16 + r + half * 8;
                *(float2*)&C[(size_t)m * SEQ + n] =
                    make_float2(acc[mt][nt][half * 2], acc[mt][nt][half * 2 + 1]);
            }
        }
    }
}

// ============================================================================
// K4: row softmax in place + emit P single fp16 plane.
// ============================================================================
__global__ __launch_bounds__(256)
void softmax_kernel(float* attn_out)
{
    float* attn = attn_out ? attn_out : g_attn;
    float* p = attn + (size_t)blockIdx.x * SEQ;
    const size_t pbase = (size_t)blockIdx.x * SEQ;
    const int tid = threadIdx.x;
    __shared__ float red_max[8];
    __shared__ float red_sum[8];

    float4 v = reinterpret_cast<float4*>(p)[tid];
    float m = fmaxf(fmaxf(v.x, v.y), fmaxf(v.z, v.w));
#pragma unroll
    for (int o = 16; o > 0; o >>= 1) m = fmaxf(m, __shfl_xor_sync(0xFFFFFFFFu, m, o));
    if ((tid & 31) == 0) red_max[tid >> 5] = m;
    __syncthreads();
    if (tid == 0) {
        float t = red_max[0];
#pragma unroll
        for (int i = 1; i < 8; i++) t = fmaxf(t, red_max[i]);
        red_max[0] = t;
    }
    __syncthreads();
    const float rmax = red_max[0];

    v.x = __expf(v.x - rmax); v.y = __expf(v.y - rmax);
    v.z = __expf(v.z - rmax); v.w = __expf(v.w - rmax);
    float s = v.x + v.y + v.z + v.w;
#pragma unroll
    for (int o = 16; o > 0; o >>= 1) s += __shfl_xor_sync(0xFFFFFFFFu, s, o);
    if ((tid & 31) == 0) red_sum[tid >> 5] = s;
    __syncthreads();
    if (tid == 0) {
        float t = 0.f;
#pragma unroll
        for (int i = 0; i < 8; i++) t += red_sum[i];
        red_sum[0] = t;
    }
    __syncthreads();
    const float inv = 1.0f / red_sum[0];
    v.x *= inv; v.y *= inv; v.z *= inv; v.w *= inv;
    reinterpret_cast<float4*>(p)[tid] = v;

    size_t idx = pbase + tid * 4;
    *(uint2*)&g_pf[idx] = make_uint2(
        pack_h2(__float2half_rn(v.x), __float2half_rn(v.y)),
        pack_h2(__float2half_rn(v.z), __float2half_rn(v.w)));
}

// ============================================================================
// K5: O = P @ vt^T per (b,h).  fp16 2-term: P single, vt hi/lo.  128x64 K=1024.
// ============================================================================
__global__ __launch_bounds__(256)
void o_mma()
{
    float acc[2][4][4];
#pragma unroll
    for (int a = 0; a < 2; a++)
#pragma unroll
        for (int b = 0; b < 4; b++)
#pragma unroll
            for (int c = 0; c < 4; c++) acc[a][b][c] = 0.f;

    const int bh = blockIdx.y, bx = blockIdx.x;
    const int b = bh / NUM_HEADS, h = bh - b * NUM_HEADS;
    gemm_tile_2t<64>(g_pf + (size_t)bh * SEQ * SEQ + (size_t)(bx * 128) * SEQ, SEQ,
                     g_vfth + (size_t)bh * HEAD_DIM * SEQ,
                     g_vftl + (size_t)bh * HEAD_DIM * SEQ, SEQ,
                     SEQ, acc);

    const int lane = threadIdx.x & 31, warp = threadIdx.x >> 5;
    const int wm = (warp >> 1) * 32, wn = (warp & 1) * 32;
    const int r = lane >> 2, cc = (lane & 3) * 2;

#pragma unroll
    for (int mt = 0; mt < 2; mt++) {
#pragma unroll
        for (int nt = 0; nt < 4; nt++) {
            int d = wn + nt * 8 + cc;
#pragma unroll
            for (int half = 0; half < 2; half++) {
                int mseq = bx * 128 + wm + mt * 16 + r + half * 8;
                size_t idx = ((size_t)b * SEQ + mseq) * DIMC + h * HEAD_DIM + d;
                *(__half2*)&g_of[idx] = __half2(
                    __float2half_rn(acc[mt][nt][half * 2]),
                    __float2half_rn(acc[mt][nt][half * 2 + 1]));
            }
        }
    }
}

// ============================================================================
// K6: out = O @ w_proj^T + bias.  fp16 2-term: O single, wp hi/lo.  fp32 out.
// ============================================================================
__global__ __launch_bounds__(256)
void proj_mma(const float* __restrict__ bias, float* out_ptr)
{
    float* outp = out_ptr ? out_ptr : g_outs;
    float acc[2][8][4];
#pragma unroll
    for (int a = 0; a < 2; a++)
#pragma unroll
        for (int b = 0; b < 8; b++)
#pragma unroll
            for (int c = 0; c < 4; c++) acc[a][b][c] = 0.f;

    const int bx = blockIdx.x, by = blockIdx.y;
    gemm_tile_2t<128>(g_of + (size_t)(by * 128) * DIMC, DIMC,
                      g_wpfh + (size_t)(bx * 128) * DIMC,
                      g_wpfl + (size_t)(bx * 128) * DIMC, DIMC,
                      DIMC, acc);

    const int lane = threadIdx.x & 31, warp = threadIdx.x >> 5;
    const int wm = (warp >> 1) * 32, wn = (warp & 1) * 64;
    const int r = lane >> 2, cc = (lane & 3) * 2;

#pragma unroll
    for (int mt = 0; mt < 2; mt++) {
#pragma unroll
        for (int nt = 0; nt < 8; nt++) {
            int n = bx * 128 + wn + nt * 8 + cc;
            float b0 = bias[n], b1 = bias[n + 1];
#pragma unroll
            for (int half = 0; half < 2; half++) {
                int m = by * 128 + wm + mt * 16 + r + half * 8;
                *(float2*)&outp[(size_t)m * DIMC + n] =
                    make_float2(acc[mt][nt][half * 2] + b0, acc[mt][nt][half * 2 + 1] + b1);
            }
        }
    }
}

// ============================================================================
// launch (serial, default stream)
// ============================================================================
extern "C" void kernel_launch(void* const* d_in, const int* in_sizes, int n_in,
                              void* d_out, int out_size)
{
    const float* x      = (const float*)d_in[0];
    const float* w_qkv  = (const float*)d_in[1];
    const float* w_proj = (const float*)d_in[2];
    const float* b_proj = (const float*)d_in[3];
    (void)in_sizes; (void)n_in;

    float* dof = (float*)d_out;
    float* out_ptr  = nullptr;
    float* attn_ptr = nullptr;
    size_t osz = (size_t)out_size;
    if (osz >= OUT_ELEMS + ATTN_ELEMS) { out_ptr = dof; attn_ptr = dof + OUT_ELEMS; }
    else if (osz == ATTN_ELEMS)        { attn_ptr = dof; }
    else                               { out_ptr = dof; }

    const int SM_2T  = 2 * (128 * SPAD * 2 + 2 * 128 * SPAD * 2);      // 61440
    const int SM_O2  = 2 * (128 * SPAD * 2 + 2 * 64 * SPAD * 2);       // 40960
    cudaFuncSetAttribute(qkv_mma,  cudaFuncAttributeMaxDynamicSharedMemorySize, SM_2T);
    cudaFuncSetAttribute(s_mma,    cudaFuncAttributeMaxDynamicSharedMemorySize, SM_2T);
    cudaFuncSetAttribute(proj_mma, cudaFuncAttributeMaxDynamicSharedMemorySize, SM_2T);
    cudaFuncSetAttribute(o_mma,    cudaFuncAttributeMaxDynamicSharedMemorySize, SM_O2);

    dim3 blk(256);

    split_all_kernel<<<(N4_TOTAL + 255) / 256, blk>>>(
        (const float4*)x, (const float4*)w_qkv, (const float4*)w_proj);

    qkv_mma<<<dim3(QKV_N / 128, M_TOK / 128), blk, SM_2T>>>();

    s_mma<<<dim3(SEQ / 128, SEQ / 128, BH), blk, SM_2T>>>(attn_ptr);

    softmax_kernel<<<dim3(BH * SEQ), blk>>>(attn_ptr);

    o_mma<<<dim3(SEQ / 128, BH), blk, SM_O2>>>();

    proj_mma<<<dim3(DIMC / 128, M_TOK / 128), blk, SM_2T>>>(b_proj, out_ptr);
}